// round 1
// baseline (speedup 1.0000x reference)
#include <cuda_runtime.h>
#include <math.h>

#define B_SZ     4
#define L_SZ     4096
#define BL       (B_SZ * L_SZ)
#define DMODEL   1024
#define DINNER   2048
#define NHEADS   32
#define HDIM     64
#define DSTATE   64
#define CONVDIM  2176
#define DPROJ    4256
#define DPROJ_PAD 4352
#define NCHUNK   64
#define CHUNK_T  64
#define SMP      68   // padded smem row stride (floats)

// ---------------- scratch (device globals; no allocation allowed) ----------------
__device__ float g_zx[(size_t)BL * DPROJ_PAD];                       // in_proj output (padded)
__device__ float g_xbc[(size_t)BL * CONVDIM];                        // conv+silu output
__device__ float g_dt[(size_t)B_SZ * NHEADS * L_SZ];                 // softplus(dt)
__device__ float g_states[(size_t)B_SZ * NCHUNK * NHEADS * HDIM * DSTATE]; // [b][c][h][n][p]
__device__ float g_acs[(size_t)B_SZ * NHEADS * NCHUNK * CHUNK_T];    // chunk-local cumsum of A*dt
__device__ float g_y[(size_t)BL * DINNER];                           // Y, then normalized y

// ---------------- GEMM: C[M,N] = A[M,K] * W[N,K]^T (both K-major) ----------------
// grid: (ceil(N/128), M/128), 256 threads. W rows guarded by Nreal.
__global__ __launch_bounds__(256) void sgemm_nt(
    const float* __restrict__ A, const float* __restrict__ W,
    float* __restrict__ C, int K, int Nreal, int lda, int ldc)
{
    __shared__ float As[16][132];
    __shared__ float Ws[16][132];
    const int tid = threadIdx.x;
    const int tx = tid & 15, ty = tid >> 4;
    const int bx = blockIdx.x, by = blockIdx.y;
    const int loadRow = tid >> 2;        // 0..63
    const int loadCol = (tid & 3) * 4;   // 0,4,8,12

    const float* Aptr = A + (size_t)(by * 128 + loadRow) * lda + loadCol;
    const int n0 = bx * 128 + loadRow;
    const float* Wptr = W + (size_t)n0 * K + loadCol;

    float acc[8][8];
    #pragma unroll
    for (int i = 0; i < 8; i++)
        #pragma unroll
        for (int j = 0; j < 8; j++) acc[i][j] = 0.f;

    for (int kt = 0; kt < K; kt += 16) {
        float4 a0 = *(const float4*)(Aptr + kt);
        float4 a1 = *(const float4*)(Aptr + (size_t)64 * lda + kt);
        float4 w0 = make_float4(0.f, 0.f, 0.f, 0.f);
        float4 w1 = make_float4(0.f, 0.f, 0.f, 0.f);
        if (n0 < Nreal)      w0 = *(const float4*)(Wptr + kt);
        if (n0 + 64 < Nreal) w1 = *(const float4*)(Wptr + (size_t)64 * K + kt);

        As[loadCol + 0][loadRow] = a0.x; As[loadCol + 1][loadRow] = a0.y;
        As[loadCol + 2][loadRow] = a0.z; As[loadCol + 3][loadRow] = a0.w;
        As[loadCol + 0][loadRow + 64] = a1.x; As[loadCol + 1][loadRow + 64] = a1.y;
        As[loadCol + 2][loadRow + 64] = a1.z; As[loadCol + 3][loadRow + 64] = a1.w;
        Ws[loadCol + 0][loadRow] = w0.x; Ws[loadCol + 1][loadRow] = w0.y;
        Ws[loadCol + 2][loadRow] = w0.z; Ws[loadCol + 3][loadRow] = w0.w;
        Ws[loadCol + 0][loadRow + 64] = w1.x; Ws[loadCol + 1][loadRow + 64] = w1.y;
        Ws[loadCol + 2][loadRow + 64] = w1.z; Ws[loadCol + 3][loadRow + 64] = w1.w;
        __syncthreads();

        #pragma unroll
        for (int kk = 0; kk < 16; kk++) {
            float af[8], wf[8];
            *(float4*)(af)     = *(const float4*)&As[kk][ty * 8];
            *(float4*)(af + 4) = *(const float4*)&As[kk][ty * 8 + 4];
            *(float4*)(wf)     = *(const float4*)&Ws[kk][tx * 8];
            *(float4*)(wf + 4) = *(const float4*)&Ws[kk][tx * 8 + 4];
            #pragma unroll
            for (int i = 0; i < 8; i++)
                #pragma unroll
                for (int j = 0; j < 8; j++)
                    acc[i][j] += af[i] * wf[j];
        }
        __syncthreads();
    }

    #pragma unroll
    for (int i = 0; i < 8; i++) {
        float* Cp = C + (size_t)(by * 128 + ty * 8 + i) * ldc + bx * 128 + tx * 8;
        *(float4*)(Cp)     = make_float4(acc[i][0], acc[i][1], acc[i][2], acc[i][3]);
        *(float4*)(Cp + 4) = make_float4(acc[i][4], acc[i][5], acc[i][6], acc[i][7]);
    }
}

// ---------------- conv1d(k=4) + SiLU ----------------
__global__ __launch_bounds__(128) void conv_silu_kernel(
    const float* __restrict__ cw, const float* __restrict__ cb)
{
    const int c = blockIdx.x * 128 + threadIdx.x;
    const int bl = blockIdx.y;
    if (c >= CONVDIM) return;
    const int b = bl >> 12, l = bl & 4095;
    float w0 = cw[c * 4 + 0], w1 = cw[c * 4 + 1], w2 = cw[c * 4 + 2], w3 = cw[c * 4 + 3];
    const float* base = g_zx + (size_t)(b * L_SZ) * DPROJ_PAD + 2048 + c;
    float acc = cb[c];
    if (l >= 3) acc += base[(size_t)(l - 3) * DPROJ_PAD] * w0;
    if (l >= 2) acc += base[(size_t)(l - 2) * DPROJ_PAD] * w1;
    if (l >= 1) acc += base[(size_t)(l - 1) * DPROJ_PAD] * w2;
    acc += base[(size_t)l * DPROJ_PAD] * w3;
    acc = acc / (1.f + __expf(-acc));
    g_xbc[(size_t)bl * CONVDIM + c] = acc;
}

// ---------------- dt = softplus(raw + bias), stored [b][h][l] ----------------
__global__ __launch_bounds__(256) void dt_kernel(const float* __restrict__ dt_bias)
{
    const int idx = blockIdx.x * 256 + threadIdx.x;
    if (idx >= BL * NHEADS) return;
    const int bl = idx >> 5, h = idx & 31;
    float v = g_zx[(size_t)bl * DPROJ_PAD + 4224 + h] + dt_bias[h];
    float sp = (v > 20.f) ? v : log1pf(__expf(v));
    const int b = bl >> 12, l = bl & 4095;
    g_dt[((size_t)(b * NHEADS + h) << 12) + l] = sp;
}

// ---------------- per-chunk SSM: Y_diag + chunk states ----------------
// grid (NCHUNK, NHEADS, B_SZ), 256 threads, dynamic smem
__global__ __launch_bounds__(256) void ssm_chunk_kernel(const float* __restrict__ A_log)
{
    extern __shared__ float sm[];
    float* Bt  = sm;                 // [n][t], n-major
    float* Ct  = Bt + 64 * SMP;      // [n][t]
    float* Xs  = Ct + 64 * SMP;      // [t][p]
    float* Gs  = Xs + 64 * SMP;      // [t][t]
    float* cs  = Gs + 64 * SMP;      // 64
    float* dec = cs + 64;            // 64
    float* dts = dec + 64;           // 64

    const int ch = blockIdx.x, h = blockIdx.y, b = blockIdx.z;
    const int tid = threadIdx.x;
    const int l0 = ch * CHUNK_T;

    if (tid < 64) {
        float dtv = g_dt[((size_t)(b * NHEADS + h) << 12) + l0 + tid];
        dts[tid] = dtv;
        float v = -__expf(A_log[h]) * dtv;
        #pragma unroll
        for (int o = 1; o < 32; o <<= 1) {
            float u = __shfl_up_sync(0xffffffffu, v, o);
            if ((tid & 31) >= o) v += u;
        }
        cs[tid] = v;
    }
    __syncthreads();
    if (tid >= 32 && tid < 64) cs[tid] += cs[31];
    __syncthreads();
    if (tid < 64) {
        dec[tid] = __expf(cs[63] - cs[tid]);
        g_acs[(size_t)((b * NHEADS + h) * NCHUNK + ch) * CHUNK_T + tid] = cs[tid];
    }
    for (int e = tid; e < 64 * 64; e += 256) {
        const int t = e >> 6, n = e & 63;
        const float* xb = g_xbc + (size_t)(b * L_SZ + l0 + t) * CONVDIM;
        Bt[n * SMP + t] = xb[2048 + n];
        Ct[n * SMP + t] = xb[2112 + n];
        Xs[t * SMP + n] = xb[h * HDIM + n] * dts[t];
    }
    __syncthreads();

    const int tx = tid & 15, ty = tid >> 4;
    const int i0 = ty * 4, j0 = tx * 4;

    // G = C * B^T (masked)
    float accG[4][4] = {};
    #pragma unroll 8
    for (int k = 0; k < 64; k++) {
        float cf[4], bf[4];
        *(float4*)cf = *(const float4*)&Ct[k * SMP + i0];
        *(float4*)bf = *(const float4*)&Bt[k * SMP + j0];
        #pragma unroll
        for (int a = 0; a < 4; a++)
            #pragma unroll
            for (int q = 0; q < 4; q++)
                accG[a][q] += cf[a] * bf[q];
    }
    #pragma unroll
    for (int a = 0; a < 4; a++) {
        const int i = i0 + a;
        float gv[4];
        #pragma unroll
        for (int q = 0; q < 4; q++) {
            const int j = j0 + q;
            gv[q] = (i >= j) ? accG[a][q] * __expf(cs[i] - cs[j]) : 0.f;
        }
        *(float4*)&Gs[i * SMP + j0] = *(float4*)gv;
    }
    __syncthreads();

    // Y_diag = G @ X
    float accY[4][4] = {};
    #pragma unroll 4
    for (int k = 0; k < 64; k += 4) {
        float xv[4][4];
        #pragma unroll
        for (int kk = 0; kk < 4; kk++)
            *(float4*)xv[kk] = *(const float4*)&Xs[(k + kk) * SMP + j0];
        #pragma unroll
        for (int a = 0; a < 4; a++) {
            float gv[4];
            *(float4*)gv = *(const float4*)&Gs[(i0 + a) * SMP + k];
            #pragma unroll
            for (int kk = 0; kk < 4; kk++)
                #pragma unroll
                for (int q = 0; q < 4; q++)
                    accY[a][q] += gv[kk] * xv[kk][q];
        }
    }
    #pragma unroll
    for (int a = 0; a < 4; a++) {
        const size_t bl = (size_t)(b * L_SZ + l0 + i0 + a);
        *(float4*)&g_y[bl * DINNER + h * HDIM + j0] = *(float4*)accY[a];
    }

    // S[n][p] = sum_t B[t][n] * dec[t] * X[t][p]
    float accS[4][4] = {};
    #pragma unroll 8
    for (int t = 0; t < 64; t++) {
        const float d = dec[t];
        float xv[4];
        *(float4*)xv = *(const float4*)&Xs[t * SMP + j0];
        float bd[4];
        #pragma unroll
        for (int a = 0; a < 4; a++) bd[a] = Bt[(i0 + a) * SMP + t] * d;
        #pragma unroll
        for (int a = 0; a < 4; a++)
            #pragma unroll
            for (int q = 0; q < 4; q++)
                accS[a][q] += bd[a] * xv[q];
    }
    const size_t sbase = ((size_t)(b * NCHUNK + ch) * NHEADS + h) * (HDIM * DSTATE);
    #pragma unroll
    for (int a = 0; a < 4; a++)
        *(float4*)&g_states[sbase + (size_t)(i0 + a) * HDIM + j0] = *(float4*)accS[a];
}

// ---------------- inter-chunk state recurrence (sequential over chunks) ----------------
__global__ __launch_bounds__(256) void ssm_state_scan(const float* __restrict__ init_states)
{
    const int bh = blockIdx.x;
    const int b = bh >> 5, h = bh & 31;
    const int tid = threadIdx.x;
    float S[16];
    #pragma unroll
    for (int r = 0; r < 16; r++) {
        const int e = tid + (r << 8);
        const int n = e >> 6, p = e & 63;
        S[r] = init_states[h * (HDIM * DSTATE) + p * DSTATE + n];
    }
    const float* acs = g_acs + (size_t)(b * NHEADS + h) * NCHUNK * CHUNK_T;
    for (int ch = 0; ch < NCHUNK; ch++) {
        const float aexp = __expf(acs[ch * CHUNK_T + 63]);
        float* st = g_states + ((size_t)(b * NCHUNK + ch) * NHEADS + h) * (HDIM * DSTATE);
        #pragma unroll
        for (int r = 0; r < 16; r++) {
            const int e = tid + (r << 8);
            const float tmp = st[e];
            st[e] = S[r];
            S[r] = aexp * S[r] + tmp;
        }
    }
}

// ---------------- Y_off = C @ S_in * exp(cs) ; final Y ----------------
__global__ __launch_bounds__(256) void ssm_out_kernel(const float* __restrict__ Dvec)
{
    __shared__ float Ct[64 * SMP];
    __shared__ float Ss[64 * SMP];
    __shared__ float scs[64];
    const int ch = blockIdx.x, h = blockIdx.y, b = blockIdx.z;
    const int tid = threadIdx.x;
    const int l0 = ch * CHUNK_T;
    const size_t sbase = ((size_t)(b * NCHUNK + ch) * NHEADS + h) * (HDIM * DSTATE);

    if (tid < 64)
        scs[tid] = __expf(g_acs[(size_t)((b * NHEADS + h) * NCHUNK + ch) * CHUNK_T + tid]);
    for (int e = tid; e < 64 * 64; e += 256) {
        const int t = e >> 6, n = e & 63;
        Ct[n * SMP + t] = g_xbc[(size_t)(b * L_SZ + l0 + t) * CONVDIM + 2112 + n];
        Ss[t * SMP + n] = g_states[sbase + e];   // here t indexes n-dim, n indexes p-dim
    }
    __syncthreads();

    const int tx = tid & 15, ty = tid >> 4;
    const int i0 = ty * 4, j0 = tx * 4;
    float acc[4][4] = {};
    #pragma unroll 8
    for (int k = 0; k < 64; k++) {
        float cf[4], sv[4];
        *(float4*)cf = *(const float4*)&Ct[k * SMP + i0];
        *(float4*)sv = *(const float4*)&Ss[k * SMP + j0];
        #pragma unroll
        for (int a = 0; a < 4; a++)
            #pragma unroll
            for (int q = 0; q < 4; q++)
                acc[a][q] += cf[a] * sv[q];
    }
    const float Dh = Dvec[h];
    #pragma unroll
    for (int a = 0; a < 4; a++) {
        const int t = i0 + a;
        const size_t bl = (size_t)(b * L_SZ + l0 + t);
        const float sc = scs[t];
        float yv[4], xv[4];
        *(float4*)yv = *(const float4*)&g_y[bl * DINNER + h * HDIM + j0];
        *(float4*)xv = *(const float4*)&g_xbc[bl * CONVDIM + h * HDIM + j0];
        #pragma unroll
        for (int q = 0; q < 4; q++)
            yv[q] = yv[q] + acc[a][q] * sc + xv[q] * Dh;
        *(float4*)&g_y[bl * DINNER + h * HDIM + j0] = *(float4*)yv;
    }
}

// ---------------- gated SiLU + RMSNorm ----------------
__global__ __launch_bounds__(256) void gate_norm_kernel(const float* __restrict__ norm_w)
{
    __shared__ float vbuf[DINNER];
    __shared__ float rsh[9];
    const int row = blockIdx.x, tid = threadIdx.x;
    const float* zr = g_zx + (size_t)row * DPROJ_PAD;
    float* yr = g_y + (size_t)row * DINNER;
    float local = 0.f;
    for (int j = tid; j < DINNER; j += 256) {
        const float z = zr[j];
        const float y = yr[j];
        const float v = y * (z / (1.f + __expf(-z)));
        vbuf[j] = v;
        local += v * v;
    }
    #pragma unroll
    for (int o = 16; o > 0; o >>= 1) local += __shfl_down_sync(0xffffffffu, local, o);
    if ((tid & 31) == 0) rsh[tid >> 5] = local;
    __syncthreads();
    if (tid == 0) {
        float s = 0.f;
        for (int w = 0; w < 8; w++) s += rsh[w];
        rsh[8] = rsqrtf(s / (float)DINNER + 1e-5f);
    }
    __syncthreads();
    const float scale = rsh[8];
    for (int j = tid; j < DINNER; j += 256)
        yr[j] = vbuf[j] * scale * norm_w[j];
}

// ---------------- host launcher ----------------
extern "C" void kernel_launch(void* const* d_in, const int* in_sizes, int n_in,
                              void* d_out, int out_size)
{
    const float* u          = (const float*)d_in[0];
    const float* in_proj_w  = (const float*)d_in[1];
    const float* conv_w     = (const float*)d_in[2];
    const float* conv_b     = (const float*)d_in[3];
    const float* init_state = (const float*)d_in[4];
    const float* dt_bias    = (const float*)d_in[5];
    const float* A_log      = (const float*)d_in[6];
    const float* Dv         = (const float*)d_in[7];
    const float* norm_w     = (const float*)d_in[8];
    const float* out_proj_w = (const float*)d_in[9];
    float* out = (float*)d_out;

    float *zx_ptr = nullptr, *y_ptr = nullptr;
    cudaGetSymbolAddress((void**)&zx_ptr, g_zx);
    cudaGetSymbolAddress((void**)&y_ptr, g_y);

    const int ssm_smem = (4 * 64 * SMP + 3 * 64) * sizeof(float);  // 70400 B
    cudaFuncSetAttribute(ssm_chunk_kernel, cudaFuncAttributeMaxDynamicSharedMemorySize, ssm_smem);

    // 1. in_proj GEMM: (16384 x 4256) = u (16384 x 1024) * W^T
    sgemm_nt<<<dim3(DPROJ_PAD / 128, BL / 128), 256>>>(u, in_proj_w, zx_ptr,
                                                       DMODEL, DPROJ, DMODEL, DPROJ_PAD);
    // 2. conv1d + SiLU
    conv_silu_kernel<<<dim3(CONVDIM / 128, BL), 128>>>(conv_w, conv_b);
    // 3. dt softplus
    dt_kernel<<<(BL * NHEADS + 255) / 256, 256>>>(dt_bias);
    // 4. per-chunk SSM
    ssm_chunk_kernel<<<dim3(NCHUNK, NHEADS, B_SZ), 256, ssm_smem>>>(A_log);
    // 5. inter-chunk recurrence
    ssm_state_scan<<<B_SZ * NHEADS, 256>>>(init_state);
    // 6. Y_off + combine
    ssm_out_kernel<<<dim3(NCHUNK, NHEADS, B_SZ), 256>>>(Dv);
    // 7. gate + rmsnorm
    gate_norm_kernel<<<BL, 256>>>(norm_w);
    // 8. out_proj GEMM: (16384 x 1024) = y (16384 x 2048) * W^T
    sgemm_nt<<<dim3(DMODEL / 128, BL / 128), 256>>>(y_ptr, out_proj_w, out,
                                                    DINNER, DMODEL, DINNER, DMODEL);
}

// round 11
// speedup vs baseline: 1.8958x; 1.8958x over previous
#include <cuda_runtime.h>
#include <cuda_bf16.h>
#include <stdint.h>
#include <cstdint>
#include <math.h>

#define B_SZ     4
#define L_SZ     4096
#define BL       (B_SZ * L_SZ)
#define DMODEL   1024
#define DINNER   2048
#define NHEADS   32
#define HDIM     64
#define DSTATE   64
#define CONVDIM  2176
#define DPROJ    4256
#define DPROJ_PAD 4352
#define NCHUNK   64
#define CHUNK_T  64
#define SMP      68

// ---------------- scratch (device globals) ----------------
__device__ float g_zx[(size_t)BL * DPROJ_PAD];
__device__ float g_xbc[(size_t)BL * CONVDIM];
__device__ float g_dt[(size_t)B_SZ * NHEADS * L_SZ];
__device__ float g_states[(size_t)B_SZ * NCHUNK * NHEADS * HDIM * DSTATE];
__device__ float g_acs[(size_t)B_SZ * NHEADS * NCHUNK * CHUNK_T];
__device__ float g_y[(size_t)BL * DINNER];

// bf16 split buffers (uint4 = 8 bf16, 16B aligned)
__device__ uint4 g_uhi[(size_t)BL * DMODEL / 8];
__device__ uint4 g_ulo[(size_t)BL * DMODEL / 8];
__device__ uint4 g_wih[(size_t)DPROJ_PAD * DMODEL / 8];
__device__ uint4 g_wil[(size_t)DPROJ_PAD * DMODEL / 8];
__device__ uint4 g_yh [(size_t)BL * DINNER / 8];
__device__ uint4 g_yl [(size_t)BL * DINNER / 8];
__device__ uint4 g_woh[(size_t)DMODEL * DINNER / 8];
__device__ uint4 g_wol[(size_t)DMODEL * DINNER / 8];

// ---------------- helpers ----------------
__device__ __forceinline__ uint32_t cvta_smem(const void* p) {
    uint32_t a;
    asm("{ .reg .u64 t; cvta.to.shared.u64 t, %1; cvt.u32.u64 %0, t; }" : "=r"(a) : "l"(p));
    return a;
}
__device__ __forceinline__ void cpasync16(uint32_t dst, const void* src) {
    asm volatile("cp.async.ca.shared.global [%0], [%1], 16;" :: "r"(dst), "l"(src));
}
__device__ __forceinline__ void cp_commit() {
    asm volatile("cp.async.commit_group;" ::: "memory");
}
template <int N> __device__ __forceinline__ void cp_wait() {
    asm volatile("cp.async.wait_group %0;" :: "n"(N) : "memory");
}
#define LDSM4(r, addr) \
    asm volatile("ldmatrix.sync.aligned.m8n8.x4.shared.b16 {%0,%1,%2,%3}, [%4];" \
        : "=r"((r)[0]), "=r"((r)[1]), "=r"((r)[2]), "=r"((r)[3]) : "r"(addr))
#define MMA16816(acc, a, b0, b1) \
    asm volatile("mma.sync.aligned.m16n8k16.row.col.f32.bf16.bf16.f32 " \
        "{%0,%1,%2,%3}, {%4,%5,%6,%7}, {%8,%9}, {%0,%1,%2,%3};" \
        : "+f"((acc)[0]), "+f"((acc)[1]), "+f"((acc)[2]), "+f"((acc)[3]) \
        : "r"((a)[0]), "r"((a)[1]), "r"((a)[2]), "r"((a)[3]), "r"(b0), "r"(b1))

// ---------------- fp32 -> bf16 hi/lo split (with row padding) ----------------
__global__ __launch_bounds__(256) void split_bf16_kernel(
    const float* __restrict__ src, uint4* __restrict__ hi, uint4* __restrict__ lo,
    int n8, int rowShift, int realRows)
{
    int idx = blockIdx.x * 256 + threadIdx.x;
    if (idx >= n8) return;
    int row = idx >> rowShift;
    uint4 H = make_uint4(0, 0, 0, 0), L = make_uint4(0, 0, 0, 0);
    if (row < realRows) {
        float4 a = ((const float4*)src)[2 * (size_t)idx];
        float4 b = ((const float4*)src)[2 * (size_t)idx + 1];
        float v[8] = {a.x, a.y, a.z, a.w, b.x, b.y, b.z, b.w};
        uint32_t hw[4], lw[4];
        #pragma unroll
        for (int p = 0; p < 4; p++) {
            __nv_bfloat16 h0 = __float2bfloat16_rn(v[2 * p]);
            __nv_bfloat16 h1 = __float2bfloat16_rn(v[2 * p + 1]);
            __nv_bfloat16 l0 = __float2bfloat16_rn(v[2 * p] - __bfloat162float(h0));
            __nv_bfloat16 l1 = __float2bfloat16_rn(v[2 * p + 1] - __bfloat162float(h1));
            __nv_bfloat162 hp = __halves2bfloat162(h0, h1);
            __nv_bfloat162 lp = __halves2bfloat162(l0, l1);
            hw[p] = *reinterpret_cast<uint32_t*>(&hp);
            lw[p] = *reinterpret_cast<uint32_t*>(&lp);
        }
        H = make_uint4(hw[0], hw[1], hw[2], hw[3]);
        L = make_uint4(lw[0], lw[1], lw[2], lw[3]);
    }
    hi[idx] = H;
    lo[idx] = L;
}

// ---------------- mma.sync GEMM: C[M,N] = A[M,K] * W[N,K]^T, 3-term bf16 ----------------
// BM=128, BN=128, BK=32; 256 threads = 8 warps (2 x 4); warp tile 64x32.
#define ROWB     80                    // smem row stride bytes (32 bf16 + pad)
#define STG_MAT  (128 * ROWB)          // 10240 B per matrix tile
#define STG_BYTES (4 * STG_MAT)        // Ah, Al, Wh, Wl
#define MMA_SMEM (2 * STG_BYTES)       // 81920 B double-buffered

__device__ __forceinline__ void gemm_load_stage(
    uint32_t base, const uint4* __restrict__ Ahi, const uint4* __restrict__ Alo,
    const uint4* __restrict__ Whi, const uint4* __restrict__ Wlo,
    size_t aRow0, size_t wRow0, int K8, int kt, int tid)
{
    #pragma unroll
    for (int i = 0; i < 2; i++) {
        int idx = tid + (i << 8);
        int row = idx >> 2, c = idx & 3;
        size_t gi = (aRow0 + row) * K8 + kt * 4 + c;
        uint32_t dst = base + row * ROWB + c * 16;
        cpasync16(dst,            Ahi + gi);
        cpasync16(dst + STG_MAT,  Alo + gi);
    }
    #pragma unroll
    for (int i = 0; i < 2; i++) {
        int idx = tid + (i << 8);
        int row = idx >> 2, c = idx & 3;
        size_t gi = (wRow0 + row) * K8 + kt * 4 + c;
        uint32_t dst = base + 2 * STG_MAT + row * ROWB + c * 16;
        cpasync16(dst,            Whi + gi);
        cpasync16(dst + STG_MAT,  Wlo + gi);
    }
}

__global__ __launch_bounds__(256) void gemm_mma3(
    const uint4* __restrict__ Ahi, const uint4* __restrict__ Alo,
    const uint4* __restrict__ Whi, const uint4* __restrict__ Wlo,
    float* __restrict__ C, int K, int ldc)
{
    extern __shared__ char smch[];
    const uint32_t sb = cvta_smem(smch);
    const int tid = threadIdx.x, lane = tid & 31, wid = tid >> 5;
    const int wm = wid >> 2, wn = wid & 3;          // 2 x 4 warp grid
    const int bx = blockIdx.x, by = blockIdx.y;
    const int K8 = K >> 3;
    const int NT = K >> 5;                          // BK = 32
    const size_t aRow0 = (size_t)by * 128;
    const size_t wRow0 = (size_t)bx * 128;

    float acc[4][4][4];
    #pragma unroll
    for (int mt = 0; mt < 4; mt++)
        #pragma unroll
        for (int nf = 0; nf < 4; nf++)
            #pragma unroll
            for (int e = 0; e < 4; e++) acc[mt][nf][e] = 0.f;

    gemm_load_stage(sb,             Ahi, Alo, Whi, Wlo, aRow0, wRow0, K8, 0, tid);
    cp_commit();
    gemm_load_stage(sb + STG_BYTES, Ahi, Alo, Whi, Wlo, aRow0, wRow0, K8, 1, tid);
    cp_commit();

    // precomputed ldmatrix lane-address offsets (within tile, before mt/nt terms)
    const int aLaneRow = (lane & 7) + ((lane >> 3) & 1) * 8;
    const int aLaneCol = (lane >> 4) * 16;
    const int wLaneRow = ((lane >> 4) * 8) + (lane & 7);
    const int wLaneCol = ((lane >> 3) & 1) * 16;

    for (int kt = 0; kt < NT; kt++) {
        if (kt + 1 < NT) cp_wait<1>(); else cp_wait<0>();
        __syncthreads();
        const uint32_t Ab = sb + (kt & 1) * STG_BYTES;
        const uint32_t Wb = Ab + 2 * STG_MAT;

        #pragma unroll
        for (int ks = 0; ks < 2; ks++) {            // two k16 steps
            uint32_t ah[4][4], al[4][4];
            #pragma unroll
            for (int mt = 0; mt < 4; mt++) {
                uint32_t addr = Ab + (wm * 64 + mt * 16 + aLaneRow) * ROWB + aLaneCol + ks * 32;
                LDSM4(ah[mt], addr);
                LDSM4(al[mt], addr + STG_MAT);
            }
            uint32_t bh[8], blo[8];
            #pragma unroll
            for (int nt2 = 0; nt2 < 2; nt2++) {
                uint32_t addr = Wb + (wn * 32 + nt2 * 16 + wLaneRow) * ROWB + wLaneCol + ks * 32;
                LDSM4(bh + 4 * nt2, addr);
                LDSM4(blo + 4 * nt2, addr + STG_MAT);
            }
            #pragma unroll
            for (int mt = 0; mt < 4; mt++)
                #pragma unroll
                for (int nf = 0; nf < 4; nf++) {
                    MMA16816(acc[mt][nf], ah[mt], bh[2 * nf],  bh[2 * nf + 1]);
                    MMA16816(acc[mt][nf], ah[mt], blo[2 * nf], blo[2 * nf + 1]);
                    MMA16816(acc[mt][nf], al[mt], bh[2 * nf],  bh[2 * nf + 1]);
                }
        }
        __syncthreads();
        if (kt + 2 < NT) {
            gemm_load_stage(sb + (kt & 1) * STG_BYTES, Ahi, Alo, Whi, Wlo,
                            aRow0, wRow0, K8, kt + 2, tid);
            cp_commit();
        }
    }

    // epilogue: acc frag layout: c0,c1 = (row=l/4, col=(l%4)*2 +0/1), c2,c3 = (row+8, same cols)
    const int rBase = by * 128 + wm * 64 + (lane >> 2);
    const int cBase = bx * 128 + wn * 32 + (lane & 3) * 2;
    #pragma unroll
    for (int mt = 0; mt < 4; mt++)
        #pragma unroll
        for (int nf = 0; nf < 4; nf++) {
            float* p0 = C + (size_t)(rBase + mt * 16)     * ldc + cBase + nf * 8;
            float* p1 = C + (size_t)(rBase + mt * 16 + 8) * ldc + cBase + nf * 8;
            p0[0] = acc[mt][nf][0]; p0[1] = acc[mt][nf][1];
            p1[0] = acc[mt][nf][2]; p1[1] = acc[mt][nf][3];
        }
}

// ---------------- conv1d(k=4) + SiLU ----------------
__global__ __launch_bounds__(128) void conv_silu_kernel(
    const float* __restrict__ cw, const float* __restrict__ cb)
{
    const int c = blockIdx.x * 128 + threadIdx.x;
    const int bl = blockIdx.y;
    if (c >= CONVDIM) return;
    const int b = bl >> 12, l = bl & 4095;
    float w0 = cw[c * 4 + 0], w1 = cw[c * 4 + 1], w2 = cw[c * 4 + 2], w3 = cw[c * 4 + 3];
    const float* base = g_zx + (size_t)(b * L_SZ) * DPROJ_PAD + 2048 + c;
    float acc = cb[c];
    if (l >= 3) acc += base[(size_t)(l - 3) * DPROJ_PAD] * w0;
    if (l >= 2) acc += base[(size_t)(l - 2) * DPROJ_PAD] * w1;
    if (l >= 1) acc += base[(size_t)(l - 1) * DPROJ_PAD] * w2;
    acc += base[(size_t)l * DPROJ_PAD] * w3;
    acc = acc / (1.f + __expf(-acc));
    g_xbc[(size_t)bl * CONVDIM + c] = acc;
}

// ---------------- dt = softplus(raw + bias), stored [b][h][l] ----------------
__global__ __launch_bounds__(256) void dt_kernel(const float* __restrict__ dt_bias)
{
    const int idx = blockIdx.x * 256 + threadIdx.x;
    if (idx >= BL * NHEADS) return;
    const int bl = idx >> 5, h = idx & 31;
    float v = g_zx[(size_t)bl * DPROJ_PAD + 4224 + h] + dt_bias[h];
    float sp = (v > 20.f) ? v : log1pf(__expf(v));
    const int b = bl >> 12, l = bl & 4095;
    g_dt[((size_t)(b * NHEADS + h) << 12) + l] = sp;
}

// ---------------- per-chunk SSM: Y_diag + chunk states ----------------
__global__ __launch_bounds__(256) void ssm_chunk_kernel(const float* __restrict__ A_log)
{
    extern __shared__ float sm[];
    float* Bt  = sm;
    float* Ct  = Bt + 64 * SMP;
    float* Xs  = Ct + 64 * SMP;
    float* Gs  = Xs + 64 * SMP;
    float* cs  = Gs + 64 * SMP;
    float* dec = cs + 64;
    float* dts = dec + 64;

    const int ch = blockIdx.x, h = blockIdx.y, b = blockIdx.z;
    const int tid = threadIdx.x;
    const int l0 = ch * CHUNK_T;

    if (tid < 64) {
        float dtv = g_dt[((size_t)(b * NHEADS + h) << 12) + l0 + tid];
        dts[tid] = dtv;
        float v = -__expf(A_log[h]) * dtv;
        #pragma unroll
        for (int o = 1; o < 32; o <<= 1) {
            float u = __shfl_up_sync(0xffffffffu, v, o);
            if ((tid & 31) >= o) v += u;
        }
        cs[tid] = v;
    }
    __syncthreads();
    if (tid >= 32 && tid < 64) cs[tid] += cs[31];
    __syncthreads();
    if (tid < 64) {
        dec[tid] = __expf(cs[63] - cs[tid]);
        g_acs[(size_t)((b * NHEADS + h) * NCHUNK + ch) * CHUNK_T + tid] = cs[tid];
    }
    for (int e = tid; e < 64 * 64; e += 256) {
        const int t = e >> 6, n = e & 63;
        const float* xb = g_xbc + (size_t)(b * L_SZ + l0 + t) * CONVDIM;
        Bt[n * SMP + t] = xb[2048 + n];
        Ct[n * SMP + t] = xb[2112 + n];
        Xs[t * SMP + n] = xb[h * HDIM + n] * dts[t];
    }
    __syncthreads();

    const int tx = tid & 15, ty = tid >> 4;
    const int i0 = ty * 4, j0 = tx * 4;

    float accG[4][4] = {};
    #pragma unroll 8
    for (int k = 0; k < 64; k++) {
        float cf[4], bf[4];
        *(float4*)cf = *(const float4*)&Ct[k * SMP + i0];
        *(float4*)bf = *(const float4*)&Bt[k * SMP + j0];
        #pragma unroll
        for (int a = 0; a < 4; a++)
            #pragma unroll
            for (int q = 0; q < 4; q++)
                accG[a][q] += cf[a] * bf[q];
    }
    #pragma unroll
    for (int a = 0; a < 4; a++) {
        const int i = i0 + a;
        float gv[4];
        #pragma unroll
        for (int q = 0; q < 4; q++) {
            const int j = j0 + q;
            gv[q] = (i >= j) ? accG[a][q] * __expf(cs[i] - cs[j]) : 0.f;
        }
        *(float4*)&Gs[i * SMP + j0] = *(float4*)gv;
    }
    __syncthreads();

    float accY[4][4] = {};
    #pragma unroll 4
    for (int k = 0; k < 64; k += 4) {
        float xv[4][4];
        #pragma unroll
        for (int kk = 0; kk < 4; kk++)
            *(float4*)xv[kk] = *(const float4*)&Xs[(k + kk) * SMP + j0];
        #pragma unroll
        for (int a = 0; a < 4; a++) {
            float gv[4];
            *(float4*)gv = *(const float4*)&Gs[(i0 + a) * SMP + k];
            #pragma unroll
            for (int kk = 0; kk < 4; kk++)
                #pragma unroll
                for (int q = 0; q < 4; q++)
                    accY[a][q] += gv[kk] * xv[kk][q];
        }
    }
    #pragma unroll
    for (int a = 0; a < 4; a++) {
        const size_t bl = (size_t)(b * L_SZ + l0 + i0 + a);
        *(float4*)&g_y[bl * DINNER + h * HDIM + j0] = *(float4*)accY[a];
    }

    float accS[4][4] = {};
    #pragma unroll 8
    for (int t = 0; t < 64; t++) {
        const float d = dec[t];
        float xv[4];
        *(float4*)xv = *(const float4*)&Xs[t * SMP + j0];
        float bd[4];
        #pragma unroll
        for (int a = 0; a < 4; a++) bd[a] = Bt[(i0 + a) * SMP + t] * d;
        #pragma unroll
        for (int a = 0; a < 4; a++)
            #pragma unroll
            for (int q = 0; q < 4; q++)
                accS[a][q] += bd[a] * xv[q];
    }
    const size_t sbase = ((size_t)(b * NCHUNK + ch) * NHEADS + h) * (HDIM * DSTATE);
    #pragma unroll
    for (int a = 0; a < 4; a++)
        *(float4*)&g_states[sbase + (size_t)(i0 + a) * HDIM + j0] = *(float4*)accS[a];
}

// ---------------- inter-chunk state recurrence ----------------
__global__ __launch_bounds__(256) void ssm_state_scan(const float* __restrict__ init_states)
{
    const int bh = blockIdx.x;
    const int b = bh >> 5, h = bh & 31;
    const int tid = threadIdx.x;
    float S[16];
    #pragma unroll
    for (int r = 0; r < 16; r++) {
        const int e = tid + (r << 8);
        const int n = e >> 6, p = e & 63;
        S[r] = init_states[h * (HDIM * DSTATE) + p * DSTATE + n];
    }
    const float* acs = g_acs + (size_t)(b * NHEADS + h) * NCHUNK * CHUNK_T;
    for (int ch = 0; ch < NCHUNK; ch++) {
        const float aexp = __expf(acs[ch * CHUNK_T + 63]);
        float* st = g_states + ((size_t)(b * NCHUNK + ch) * NHEADS + h) * (HDIM * DSTATE);
        #pragma unroll
        for (int r = 0; r < 16; r++) {
            const int e = tid + (r << 8);
            const float tmp = st[e];
            st[e] = S[r];
            S[r] = aexp * S[r] + tmp;
        }
    }
}

// ---------------- Y_off = C @ S_in * exp(cs) ; final Y ----------------
__global__ __launch_bounds__(256) void ssm_out_kernel(const float* __restrict__ Dvec)
{
    __shared__ float Ct[64 * SMP];
    __shared__ float Ss[64 * SMP];
    __shared__ float scs[64];
    const int ch = blockIdx.x, h = blockIdx.y, b = blockIdx.z;
    const int tid = threadIdx.x;
    const int l0 = ch * CHUNK_T;
    const size_t sbase = ((size_t)(b * NCHUNK + ch) * NHEADS + h) * (HDIM * DSTATE);

    if (tid < 64)
        scs[tid] = __expf(g_acs[(size_t)((b * NHEADS + h) * NCHUNK + ch) * CHUNK_T + tid]);
    for (int e = tid; e < 64 * 64; e += 256) {
        const int t = e >> 6, n = e & 63;
        Ct[n * SMP + t] = g_xbc[(size_t)(b * L_SZ + l0 + t) * CONVDIM + 2112 + n];
        Ss[t * SMP + n] = g_states[sbase + e];
    }
    __syncthreads();

    const int tx = tid & 15, ty = tid >> 4;
    const int i0 = ty * 4, j0 = tx * 4;
    float acc[4][4] = {};
    #pragma unroll 8
    for (int k = 0; k < 64; k++) {
        float cf[4], sv[4];
        *(float4*)cf = *(const float4*)&Ct[k * SMP + i0];
        *(float4*)sv = *(const float4*)&Ss[k * SMP + j0];
        #pragma unroll
        for (int a = 0; a < 4; a++)
            #pragma unroll
            for (int q = 0; q < 4; q++)
                acc[a][q] += cf[a] * sv[q];
    }
    const float Dh = Dvec[h];
    #pragma unroll
    for (int a = 0; a < 4; a++) {
        const int t = i0 + a;
        const size_t bl = (size_t)(b * L_SZ + l0 + t);
        const float sc = scs[t];
        float yv[4], xv[4];
        *(float4*)yv = *(const float4*)&g_y[bl * DINNER + h * HDIM + j0];
        *(float4*)xv = *(const float4*)&g_xbc[bl * CONVDIM + h * HDIM + j0];
        #pragma unroll
        for (int q = 0; q < 4; q++)
            yv[q] = yv[q] + acc[a][q] * sc + xv[q] * Dh;
        *(float4*)&g_y[bl * DINNER + h * HDIM + j0] = *(float4*)yv;
    }
}

// ---------------- gated SiLU + RMSNorm, output split to bf16 hi/lo ----------------
__global__ __launch_bounds__(256) void gate_norm_kernel(const float* __restrict__ norm_w)
{
    __shared__ float rsh[9];
    const int row = blockIdx.x, tid = threadIdx.x;
    const float* zr = g_zx + (size_t)row * DPROJ_PAD;
    const float* yr = g_y + (size_t)row * DINNER;
    const int j0 = tid * 8;

    float4 z0 = *(const float4*)(zr + j0), z1 = *(const float4*)(zr + j0 + 4);
    float4 y0 = *(const float4*)(yr + j0), y1 = *(const float4*)(yr + j0 + 4);
    float zz[8] = {z0.x, z0.y, z0.z, z0.w, z1.x, z1.y, z1.z, z1.w};
    float yy[8] = {y0.x, y0.y, y0.z, y0.w, y1.x, y1.y, y1.z, y1.w};
    float v[8];
    float local = 0.f;
    #pragma unroll
    for (int j = 0; j < 8; j++) {
        const float s = zz[j] / (1.f + __expf(-zz[j]));
        v[j] = yy[j] * s;
        local += v[j] * v[j];
    }
    #pragma unroll
    for (int o = 16; o > 0; o >>= 1) local += __shfl_down_sync(0xffffffffu, local, o);
    if ((tid & 31) == 0) rsh[tid >> 5] = local;
    __syncthreads();
    if (tid == 0) {
        float s = 0.f;
        for (int w = 0; w < 8; w++) s += rsh[w];
        rsh[8] = rsqrtf(s / (float)DINNER + 1e-5f);
    }
    __syncthreads();
    const float scale = rsh[8];

    float4 w0 = *(const float4*)(norm_w + j0), w1 = *(const float4*)(norm_w + j0 + 4);
    float ww[8] = {w0.x, w0.y, w0.z, w0.w, w1.x, w1.y, w1.z, w1.w};
    uint32_t hw[4], lw[4];
    #pragma unroll
    for (int p = 0; p < 4; p++) {
        float a = v[2 * p] * scale * ww[2 * p];
        float b = v[2 * p + 1] * scale * ww[2 * p + 1];
        __nv_bfloat16 h0 = __float2bfloat16_rn(a);
        __nv_bfloat16 h1 = __float2bfloat16_rn(b);
        __nv_bfloat16 l0 = __float2bfloat16_rn(a - __bfloat162float(h0));
        __nv_bfloat16 l1 = __float2bfloat16_rn(b - __bfloat162float(h1));
        __nv_bfloat162 hp = __halves2bfloat162(h0, h1);
        __nv_bfloat162 lp = __halves2bfloat162(l0, l1);
        hw[p] = *reinterpret_cast<uint32_t*>(&hp);
        lw[p] = *reinterpret_cast<uint32_t*>(&lp);
    }
    const size_t oi = ((size_t)row * DINNER + j0) >> 3;
    g_yh[oi] = make_uint4(hw[0], hw[1], hw[2], hw[3]);
    g_yl[oi] = make_uint4(lw[0], lw[1], lw[2], lw[3]);
}

// ---------------- host launcher ----------------
extern "C" void kernel_launch(void* const* d_in, const int* in_sizes, int n_in,
                              void* d_out, int out_size)
{
    const float* u          = (const float*)d_in[0];
    const float* in_proj_w  = (const float*)d_in[1];
    const float* conv_w     = (const float*)d_in[2];
    const float* conv_b     = (const float*)d_in[3];
    const float* init_state = (const float*)d_in[4];
    const float* dt_bias    = (const float*)d_in[5];
    const float* A_log      = (const float*)d_in[6];
    const float* Dv         = (const float*)d_in[7];
    const float* norm_w     = (const float*)d_in[8];
    const float* out_proj_w = (const float*)d_in[9];
    float* out = (float*)d_out;

    float* zx_ptr = nullptr;
    uint4 *uhi, *ulo, *wih, *wil, *yh, *yl, *woh, *wol;
    cudaGetSymbolAddress((void**)&zx_ptr, g_zx);
    cudaGetSymbolAddress((void**)&uhi, g_uhi);
    cudaGetSymbolAddress((void**)&ulo, g_ulo);
    cudaGetSymbolAddress((void**)&wih, g_wih);
    cudaGetSymbolAddress((void**)&wil, g_wil);
    cudaGetSymbolAddress((void**)&yh,  g_yh);
    cudaGetSymbolAddress((void**)&yl,  g_yl);
    cudaGetSymbolAddress((void**)&woh, g_woh);
    cudaGetSymbolAddress((void**)&wol, g_wol);

    const int ssm_smem = (4 * 64 * SMP + 3 * 64) * sizeof(float);
    cudaFuncSetAttribute(ssm_chunk_kernel, cudaFuncAttributeMaxDynamicSharedMemorySize, ssm_smem);
    cudaFuncSetAttribute(gemm_mma3, cudaFuncAttributeMaxDynamicSharedMemorySize, MMA_SMEM);

    // 0. precision splits
    {
        int n8 = BL * DMODEL / 8;                 // u
        split_bf16_kernel<<<(n8 + 255) / 256, 256>>>(u, uhi, ulo, n8, 7, BL);
        n8 = DPROJ_PAD * DMODEL / 8;              // in_proj w (padded rows zeroed)
        split_bf16_kernel<<<(n8 + 255) / 256, 256>>>(in_proj_w, wih, wil, n8, 7, DPROJ);
        n8 = DMODEL * DINNER / 8;                 // out_proj w
        split_bf16_kernel<<<(n8 + 255) / 256, 256>>>(out_proj_w, woh, wol, n8, 8, DMODEL);
    }
    // 1. in_proj GEMM (mma.sync bf16 x3): 16384 x 4352 x 1024
    gemm_mma3<<<dim3(DPROJ_PAD / 128, BL / 128), 256, MMA_SMEM>>>(
        uhi, ulo, wih, wil, zx_ptr, DMODEL, DPROJ_PAD);
    // 2. conv1d + SiLU
    conv_silu_kernel<<<dim3(CONVDIM / 128, BL), 128>>>(conv_w, conv_b);
    // 3. dt softplus
    dt_kernel<<<(BL * NHEADS + 255) / 256, 256>>>(dt_bias);
    // 4. per-chunk SSM
    ssm_chunk_kernel<<<dim3(NCHUNK, NHEADS, B_SZ), 256, ssm_smem>>>(A_log);
    // 5. inter-chunk recurrence
    ssm_state_scan<<<B_SZ * NHEADS, 256>>>(init_state);
    // 6. Y_off + combine
    ssm_out_kernel<<<dim3(NCHUNK, NHEADS, B_SZ), 256>>>(Dv);
    // 7. gate + rmsnorm (+ bf16 split of y)
    gate_norm_kernel<<<BL, 256>>>(norm_w);
    // 8. out_proj GEMM: 16384 x 1024 x 2048
    gemm_mma3<<<dim3(DMODEL / 128, BL / 128), 256, MMA_SMEM>>>(
        yh, yl, woh, wol, out, DINNER, DMODEL);
}

// round 12
// speedup vs baseline: 2.2572x; 1.1906x over previous
#include <cuda_runtime.h>
#include <cuda_fp16.h>
#include <stdint.h>
#include <cstdint>
#include <math.h>

#define B_SZ     4
#define L_SZ     4096
#define BL       (B_SZ * L_SZ)
#define DMODEL   1024
#define DINNER   2048
#define NHEADS   32
#define HDIM     64
#define DSTATE   64
#define CONVDIM  2176
#define DPROJ    4256
#define DPROJ_PAD 4352
#define NCHUNK   64
#define CHUNK_T  64
#define SMP      68

// ---------------- scratch (device globals) ----------------
__device__ float g_zx[(size_t)BL * DPROJ_PAD];
__device__ float g_xbc[(size_t)BL * CONVDIM];
__device__ float g_dt[(size_t)B_SZ * NHEADS * L_SZ];
__device__ float g_states[(size_t)B_SZ * NCHUNK * NHEADS * HDIM * DSTATE];
__device__ float g_acs[(size_t)B_SZ * NHEADS * NCHUNK * CHUNK_T];
__device__ float g_y[(size_t)BL * DINNER];

// fp16 buffers (uint4 = 8 halfs, 16B aligned)
__device__ uint4 g_uhi[(size_t)BL * DMODEL / 8];
__device__ uint4 g_ulo[(size_t)BL * DMODEL / 8];
__device__ uint4 g_wif[(size_t)DPROJ_PAD * DMODEL / 8];
__device__ uint4 g_yh [(size_t)BL * DINNER / 8];
__device__ uint4 g_yl [(size_t)BL * DINNER / 8];
__device__ uint4 g_wof[(size_t)DMODEL * DINNER / 8];

// ---------------- helpers ----------------
__device__ __forceinline__ uint32_t cvta_smem(const void* p) {
    uint32_t a;
    asm("{ .reg .u64 t; cvta.to.shared.u64 t, %1; cvt.u32.u64 %0, t; }" : "=r"(a) : "l"(p));
    return a;
}
__device__ __forceinline__ void cpasync16(uint32_t dst, const void* src) {
    asm volatile("cp.async.ca.shared.global [%0], [%1], 16;" :: "r"(dst), "l"(src));
}
__device__ __forceinline__ void cp_commit() {
    asm volatile("cp.async.commit_group;" ::: "memory");
}
template <int N> __device__ __forceinline__ void cp_wait() {
    asm volatile("cp.async.wait_group %0;" :: "n"(N) : "memory");
}
#define LDSM4(r, addr) \
    asm volatile("ldmatrix.sync.aligned.m8n8.x4.shared.b16 {%0,%1,%2,%3}, [%4];" \
        : "=r"((r)[0]), "=r"((r)[1]), "=r"((r)[2]), "=r"((r)[3]) : "r"(addr))
#define MMA16816(acc, a, b0, b1) \
    asm volatile("mma.sync.aligned.m16n8k16.row.col.f32.f16.f16.f32 " \
        "{%0,%1,%2,%3}, {%4,%5,%6,%7}, {%8,%9}, {%0,%1,%2,%3};" \
        : "+f"((acc)[0]), "+f"((acc)[1]), "+f"((acc)[2]), "+f"((acc)[3]) \
        : "r"((a)[0]), "r"((a)[1]), "r"((a)[2]), "r"((a)[3]), "r"(b0), "r"(b1))

// ---------------- fp32 -> fp16 hi/lo split (2-term, exact A) ----------------
__global__ __launch_bounds__(256) void split2_fp16_kernel(
    const float* __restrict__ src, uint4* __restrict__ hi, uint4* __restrict__ lo,
    int n8, int rowShift, int realRows)
{
    int idx = blockIdx.x * 256 + threadIdx.x;
    if (idx >= n8) return;
    int row = idx >> rowShift;
    uint4 H = make_uint4(0, 0, 0, 0), L = make_uint4(0, 0, 0, 0);
    if (row < realRows) {
        float4 a = ((const float4*)src)[2 * (size_t)idx];
        float4 b = ((const float4*)src)[2 * (size_t)idx + 1];
        float v[8] = {a.x, a.y, a.z, a.w, b.x, b.y, b.z, b.w};
        uint32_t hw[4], lw[4];
        #pragma unroll
        for (int p = 0; p < 4; p++) {
            __half h0 = __float2half_rn(v[2 * p]);
            __half h1 = __float2half_rn(v[2 * p + 1]);
            __half l0 = __float2half_rn(v[2 * p] - __half2float(h0));
            __half l1 = __float2half_rn(v[2 * p + 1] - __half2float(h1));
            __half2 hp = __halves2half2(h0, h1);
            __half2 lp = __halves2half2(l0, l1);
            hw[p] = *reinterpret_cast<uint32_t*>(&hp);
            lw[p] = *reinterpret_cast<uint32_t*>(&lp);
        }
        H = make_uint4(hw[0], hw[1], hw[2], hw[3]);
        L = make_uint4(lw[0], lw[1], lw[2], lw[3]);
    }
    hi[idx] = H;
    lo[idx] = L;
}

// ---------------- fp32 -> single fp16 (weights) ----------------
__global__ __launch_bounds__(256) void split1_fp16_kernel(
    const float* __restrict__ src, uint4* __restrict__ out,
    int n8, int rowShift, int realRows)
{
    int idx = blockIdx.x * 256 + threadIdx.x;
    if (idx >= n8) return;
    int row = idx >> rowShift;
    uint4 H = make_uint4(0, 0, 0, 0);
    if (row < realRows) {
        float4 a = ((const float4*)src)[2 * (size_t)idx];
        float4 b = ((const float4*)src)[2 * (size_t)idx + 1];
        float v[8] = {a.x, a.y, a.z, a.w, b.x, b.y, b.z, b.w};
        uint32_t hw[4];
        #pragma unroll
        for (int p = 0; p < 4; p++) {
            __half2 hp = __halves2half2(__float2half_rn(v[2 * p]), __float2half_rn(v[2 * p + 1]));
            hw[p] = *reinterpret_cast<uint32_t*>(&hp);
        }
        H = make_uint4(hw[0], hw[1], hw[2], hw[3]);
    }
    out[idx] = H;
}

// ---------------- mma.sync GEMM: C[M,N] = A[M,K] * W[N,K]^T, 2-term fp16 ----------------
// BM=128, BN=128, BK=32; 256 threads = 8 warps (2 x 4); warp tile 64x32.
// 3-stage cp.async pipeline; stage = [Ah | Al | Wf], each 128 rows x 80B.
#define ROWB      80
#define STG_MAT   (128 * ROWB)           // 10240 B
#define STG_BYTES (3 * STG_MAT)          // 30720 B
#define MMA_SMEM  (3 * STG_BYTES)        // 92160 B, 3 stages

__device__ __forceinline__ void gemm_load_stage(
    uint32_t base, const uint4* __restrict__ Ahi, const uint4* __restrict__ Alo,
    const uint4* __restrict__ Wf,
    size_t aRow0, size_t wRow0, int K8, int kt, int tid)
{
    #pragma unroll
    for (int i = 0; i < 2; i++) {
        int idx = tid + (i << 8);
        int row = idx >> 2, c = idx & 3;
        size_t gi = (aRow0 + row) * K8 + kt * 4 + c;
        uint32_t dst = base + row * ROWB + c * 16;
        cpasync16(dst,           Ahi + gi);
        cpasync16(dst + STG_MAT, Alo + gi);
    }
    #pragma unroll
    for (int i = 0; i < 2; i++) {
        int idx = tid + (i << 8);
        int row = idx >> 2, c = idx & 3;
        size_t gi = (wRow0 + row) * K8 + kt * 4 + c;
        cpasync16(base + 2 * STG_MAT + row * ROWB + c * 16, Wf + gi);
    }
}

__global__ __launch_bounds__(256, 2) void gemm_mma2(
    const uint4* __restrict__ Ahi, const uint4* __restrict__ Alo,
    const uint4* __restrict__ Wf,
    float* __restrict__ C, int K, int ldc)
{
    extern __shared__ char smch[];
    const uint32_t sb = cvta_smem(smch);
    const int tid = threadIdx.x, lane = tid & 31, wid = tid >> 5;
    const int wm = wid >> 2, wn = wid & 3;          // 2 x 4 warp grid
    const int bx = blockIdx.x, by = blockIdx.y;
    const int K8 = K >> 3;
    const int NT = K >> 5;                          // BK = 32
    const size_t aRow0 = (size_t)by * 128;
    const size_t wRow0 = (size_t)bx * 128;

    float acc[4][4][4];
    #pragma unroll
    for (int mt = 0; mt < 4; mt++)
        #pragma unroll
        for (int nf = 0; nf < 4; nf++)
            #pragma unroll
            for (int e = 0; e < 4; e++) acc[mt][nf][e] = 0.f;

    gemm_load_stage(sb,                 Ahi, Alo, Wf, aRow0, wRow0, K8, 0, tid);
    cp_commit();
    gemm_load_stage(sb + STG_BYTES,     Ahi, Alo, Wf, aRow0, wRow0, K8, 1, tid);
    cp_commit();

    const int aLaneRow = (lane & 7) + ((lane >> 3) & 1) * 8;
    const int aLaneCol = (lane >> 4) * 16;
    const int wLaneRow = ((lane >> 4) * 8) + (lane & 7);
    const int wLaneCol = ((lane >> 3) & 1) * 16;

    int cur = 0, nxt = 2;
    for (int kt = 0; kt < NT; kt++) {
        if (kt == NT - 1) cp_wait<0>(); else cp_wait<1>();
        __syncthreads();
        const uint32_t Ab = sb + cur * STG_BYTES;
        const uint32_t Wb = Ab + 2 * STG_MAT;

        #pragma unroll
        for (int ks = 0; ks < 2; ks++) {            // two k16 steps
            uint32_t ah[4][4], al[4][4];
            #pragma unroll
            for (int mt = 0; mt < 4; mt++) {
                uint32_t addr = Ab + (wm * 64 + mt * 16 + aLaneRow) * ROWB + aLaneCol + ks * 32;
                LDSM4(ah[mt], addr);
                LDSM4(al[mt], addr + STG_MAT);
            }
            uint32_t wf[8];
            #pragma unroll
            for (int nt2 = 0; nt2 < 2; nt2++) {
                uint32_t addr = Wb + (wn * 32 + nt2 * 16 + wLaneRow) * ROWB + wLaneCol + ks * 32;
                LDSM4(wf + 4 * nt2, addr);
            }
            #pragma unroll
            for (int mt = 0; mt < 4; mt++)
                #pragma unroll
                for (int nf = 0; nf < 4; nf++) {
                    MMA16816(acc[mt][nf], ah[mt], wf[2 * nf], wf[2 * nf + 1]);
                    MMA16816(acc[mt][nf], al[mt], wf[2 * nf], wf[2 * nf + 1]);
                }
        }
        if (kt + 2 < NT) {
            gemm_load_stage(sb + nxt * STG_BYTES, Ahi, Alo, Wf, aRow0, wRow0, K8, kt + 2, tid);
            cp_commit();
        }
        cur = (cur == 2) ? 0 : cur + 1;
        nxt = (nxt == 2) ? 0 : nxt + 1;
    }

    const int rBase = by * 128 + wm * 64 + (lane >> 2);
    const int cBase = bx * 128 + wn * 32 + (lane & 3) * 2;
    #pragma unroll
    for (int mt = 0; mt < 4; mt++)
        #pragma unroll
        for (int nf = 0; nf < 4; nf++) {
            float* p0 = C + (size_t)(rBase + mt * 16)     * ldc + cBase + nf * 8;
            float* p1 = C + (size_t)(rBase + mt * 16 + 8) * ldc + cBase + nf * 8;
            p0[0] = acc[mt][nf][0]; p0[1] = acc[mt][nf][1];
            p1[0] = acc[mt][nf][2]; p1[1] = acc[mt][nf][3];
        }
}

// ---------------- conv1d(k=4) + SiLU ----------------
__global__ __launch_bounds__(128) void conv_silu_kernel(
    const float* __restrict__ cw, const float* __restrict__ cb)
{
    const int c = blockIdx.x * 128 + threadIdx.x;
    const int bl = blockIdx.y;
    if (c >= CONVDIM) return;
    const int b = bl >> 12, l = bl & 4095;
    float w0 = cw[c * 4 + 0], w1 = cw[c * 4 + 1], w2 = cw[c * 4 + 2], w3 = cw[c * 4 + 3];
    const float* base = g_zx + (size_t)(b * L_SZ) * DPROJ_PAD + 2048 + c;
    float acc = cb[c];
    if (l >= 3) acc += base[(size_t)(l - 3) * DPROJ_PAD] * w0;
    if (l >= 2) acc += base[(size_t)(l - 2) * DPROJ_PAD] * w1;
    if (l >= 1) acc += base[(size_t)(l - 1) * DPROJ_PAD] * w2;
    acc += base[(size_t)l * DPROJ_PAD] * w3;
    acc = acc / (1.f + __expf(-acc));
    g_xbc[(size_t)bl * CONVDIM + c] = acc;
}

// ---------------- dt = softplus(raw + bias), stored [b][h][l] ----------------
__global__ __launch_bounds__(256) void dt_kernel(const float* __restrict__ dt_bias)
{
    const int idx = blockIdx.x * 256 + threadIdx.x;
    if (idx >= BL * NHEADS) return;
    const int bl = idx >> 5, h = idx & 31;
    float v = g_zx[(size_t)bl * DPROJ_PAD + 4224 + h] + dt_bias[h];
    float sp = (v > 20.f) ? v : log1pf(__expf(v));
    const int b = bl >> 12, l = bl & 4095;
    g_dt[((size_t)(b * NHEADS + h) << 12) + l] = sp;
}

// ---------------- per-chunk SSM: Y_diag + chunk states ----------------
__global__ __launch_bounds__(256) void ssm_chunk_kernel(const float* __restrict__ A_log)
{
    extern __shared__ float sm[];
    float* Bt  = sm;
    float* Ct  = Bt + 64 * SMP;
    float* Xs  = Ct + 64 * SMP;
    float* Gs  = Xs + 64 * SMP;
    float* cs  = Gs + 64 * SMP;
    float* dec = cs + 64;
    float* dts = dec + 64;

    const int ch = blockIdx.x, h = blockIdx.y, b = blockIdx.z;
    const int tid = threadIdx.x;
    const int l0 = ch * CHUNK_T;

    if (tid < 64) {
        float dtv = g_dt[((size_t)(b * NHEADS + h) << 12) + l0 + tid];
        dts[tid] = dtv;
        float v = -__expf(A_log[h]) * dtv;
        #pragma unroll
        for (int o = 1; o < 32; o <<= 1) {
            float u = __shfl_up_sync(0xffffffffu, v, o);
            if ((tid & 31) >= o) v += u;
        }
        cs[tid] = v;
    }
    __syncthreads();
    if (tid >= 32 && tid < 64) cs[tid] += cs[31];
    __syncthreads();
    if (tid < 64) {
        dec[tid] = __expf(cs[63] - cs[tid]);
        g_acs[(size_t)((b * NHEADS + h) * NCHUNK + ch) * CHUNK_T + tid] = cs[tid];
    }
    for (int e = tid; e < 64 * 64; e += 256) {
        const int t = e >> 6, n = e & 63;
        const float* xb = g_xbc + (size_t)(b * L_SZ + l0 + t) * CONVDIM;
        Bt[n * SMP + t] = xb[2048 + n];
        Ct[n * SMP + t] = xb[2112 + n];
        Xs[t * SMP + n] = xb[h * HDIM + n] * dts[t];
    }
    __syncthreads();

    const int tx = tid & 15, ty = tid >> 4;
    const int i0 = ty * 4, j0 = tx * 4;

    float accG[4][4] = {};
    #pragma unroll 8
    for (int k = 0; k < 64; k++) {
        float cf[4], bf[4];
        *(float4*)cf = *(const float4*)&Ct[k * SMP + i0];
        *(float4*)bf = *(const float4*)&Bt[k * SMP + j0];
        #pragma unroll
        for (int a = 0; a < 4; a++)
            #pragma unroll
            for (int q = 0; q < 4; q++)
                accG[a][q] += cf[a] * bf[q];
    }
    #pragma unroll
    for (int a = 0; a < 4; a++) {
        const int i = i0 + a;
        float gv[4];
        #pragma unroll
        for (int q = 0; q < 4; q++) {
            const int j = j0 + q;
            gv[q] = (i >= j) ? accG[a][q] * __expf(cs[i] - cs[j]) : 0.f;
        }
        *(float4*)&Gs[i * SMP + j0] = *(float4*)gv;
    }
    __syncthreads();

    float accY[4][4] = {};
    #pragma unroll 4
    for (int k = 0; k < 64; k += 4) {
        float xv[4][4];
        #pragma unroll
        for (int kk = 0; kk < 4; kk++)
            *(float4*)xv[kk] = *(const float4*)&Xs[(k + kk) * SMP + j0];
        #pragma unroll
        for (int a = 0; a < 4; a++) {
            float gv[4];
            *(float4*)gv = *(const float4*)&Gs[(i0 + a) * SMP + k];
            #pragma unroll
            for (int kk = 0; kk < 4; kk++)
                #pragma unroll
                for (int q = 0; q < 4; q++)
                    accY[a][q] += gv[kk] * xv[kk][q];
        }
    }
    #pragma unroll
    for (int a = 0; a < 4; a++) {
        const size_t bl = (size_t)(b * L_SZ + l0 + i0 + a);
        *(float4*)&g_y[bl * DINNER + h * HDIM + j0] = *(float4*)accY[a];
    }

    float accS[4][4] = {};
    #pragma unroll 8
    for (int t = 0; t < 64; t++) {
        const float d = dec[t];
        float xv[4];
        *(float4*)xv = *(const float4*)&Xs[t * SMP + j0];
        float bd[4];
        #pragma unroll
        for (int a = 0; a < 4; a++) bd[a] = Bt[(i0 + a) * SMP + t] * d;
        #pragma unroll
        for (int a = 0; a < 4; a++)
            #pragma unroll
            for (int q = 0; q < 4; q++)
                accS[a][q] += bd[a] * xv[q];
    }
    const size_t sbase = ((size_t)(b * NCHUNK + ch) * NHEADS + h) * (HDIM * DSTATE);
    #pragma unroll
    for (int a = 0; a < 4; a++)
        *(float4*)&g_states[sbase + (size_t)(i0 + a) * HDIM + j0] = *(float4*)accS[a];
}

// ---------------- inter-chunk state recurrence ----------------
__global__ __launch_bounds__(256) void ssm_state_scan(const float* __restrict__ init_states)
{
    const int bh = blockIdx.x;
    const int b = bh >> 5, h = bh & 31;
    const int tid = threadIdx.x;
    float S[16];
    #pragma unroll
    for (int r = 0; r < 16; r++) {
        const int e = tid + (r << 8);
        const int n = e >> 6, p = e & 63;
        S[r] = init_states[h * (HDIM * DSTATE) + p * DSTATE + n];
    }
    const float* acs = g_acs + (size_t)(b * NHEADS + h) * NCHUNK * CHUNK_T;
    for (int ch = 0; ch < NCHUNK; ch++) {
        const float aexp = __expf(acs[ch * CHUNK_T + 63]);
        float* st = g_states + ((size_t)(b * NCHUNK + ch) * NHEADS + h) * (HDIM * DSTATE);
        #pragma unroll
        for (int r = 0; r < 16; r++) {
            const int e = tid + (r << 8);
            const float tmp = st[e];
            st[e] = S[r];
            S[r] = aexp * S[r] + tmp;
        }
    }
}

// ---------------- Y_off = C @ S_in * exp(cs) ; final Y ----------------
__global__ __launch_bounds__(256) void ssm_out_kernel(const float* __restrict__ Dvec)
{
    __shared__ float Ct[64 * SMP];
    __shared__ float Ss[64 * SMP];
    __shared__ float scs[64];
    const int ch = blockIdx.x, h = blockIdx.y, b = blockIdx.z;
    const int tid = threadIdx.x;
    const int l0 = ch * CHUNK_T;
    const size_t sbase = ((size_t)(b * NCHUNK + ch) * NHEADS + h) * (HDIM * DSTATE);

    if (tid < 64)
        scs[tid] = __expf(g_acs[(size_t)((b * NHEADS + h) * NCHUNK + ch) * CHUNK_T + tid]);
    for (int e = tid; e < 64 * 64; e += 256) {
        const int t = e >> 6, n = e & 63;
        Ct[n * SMP + t] = g_xbc[(size_t)(b * L_SZ + l0 + t) * CONVDIM + 2112 + n];
        Ss[t * SMP + n] = g_states[sbase + e];
    }
    __syncthreads();

    const int tx = tid & 15, ty = tid >> 4;
    const int i0 = ty * 4, j0 = tx * 4;
    float acc[4][4] = {};
    #pragma unroll 8
    for (int k = 0; k < 64; k++) {
        float cf[4], sv[4];
        *(float4*)cf = *(const float4*)&Ct[k * SMP + i0];
        *(float4*)sv = *(const float4*)&Ss[k * SMP + j0];
        #pragma unroll
        for (int a = 0; a < 4; a++)
            #pragma unroll
            for (int q = 0; q < 4; q++)
                acc[a][q] += cf[a] * sv[q];
    }
    const float Dh = Dvec[h];
    #pragma unroll
    for (int a = 0; a < 4; a++) {
        const int t = i0 + a;
        const size_t bl = (size_t)(b * L_SZ + l0 + t);
        const float sc = scs[t];
        float yv[4], xv[4];
        *(float4*)yv = *(const float4*)&g_y[bl * DINNER + h * HDIM + j0];
        *(float4*)xv = *(const float4*)&g_xbc[bl * CONVDIM + h * HDIM + j0];
        #pragma unroll
        for (int q = 0; q < 4; q++)
            yv[q] = yv[q] + acc[a][q] * sc + xv[q] * Dh;
        *(float4*)&g_y[bl * DINNER + h * HDIM + j0] = *(float4*)yv;
    }
}

// ---------------- gated SiLU + RMSNorm, output split to fp16 hi/lo ----------------
__global__ __launch_bounds__(256) void gate_norm_kernel(const float* __restrict__ norm_w)
{
    __shared__ float rsh[9];
    const int row = blockIdx.x, tid = threadIdx.x;
    const float* zr = g_zx + (size_t)row * DPROJ_PAD;
    const float* yr = g_y + (size_t)row * DINNER;
    const int j0 = tid * 8;

    float4 z0 = *(const float4*)(zr + j0), z1 = *(const float4*)(zr + j0 + 4);
    float4 y0 = *(const float4*)(yr + j0), y1 = *(const float4*)(yr + j0 + 4);
    float zz[8] = {z0.x, z0.y, z0.z, z0.w, z1.x, z1.y, z1.z, z1.w};
    float yy[8] = {y0.x, y0.y, y0.z, y0.w, y1.x, y1.y, y1.z, y1.w};
    float v[8];
    float local = 0.f;
    #pragma unroll
    for (int j = 0; j < 8; j++) {
        const float s = zz[j] / (1.f + __expf(-zz[j]));
        v[j] = yy[j] * s;
        local += v[j] * v[j];
    }
    #pragma unroll
    for (int o = 16; o > 0; o >>= 1) local += __shfl_down_sync(0xffffffffu, local, o);
    if ((tid & 31) == 0) rsh[tid >> 5] = local;
    __syncthreads();
    if (tid == 0) {
        float s = 0.f;
        for (int w = 0; w < 8; w++) s += rsh[w];
        rsh[8] = rsqrtf(s / (float)DINNER + 1e-5f);
    }
    __syncthreads();
    const float scale = rsh[8];

    float4 w0 = *(const float4*)(norm_w + j0), w1 = *(const float4*)(norm_w + j0 + 4);
    float ww[8] = {w0.x, w0.y, w0.z, w0.w, w1.x, w1.y, w1.z, w1.w};
    uint32_t hw[4], lw[4];
    #pragma unroll
    for (int p = 0; p < 4; p++) {
        float a = v[2 * p] * scale * ww[2 * p];
        float b = v[2 * p + 1] * scale * ww[2 * p + 1];
        __half h0 = __float2half_rn(a);
        __half h1 = __float2half_rn(b);
        __half l0 = __float2half_rn(a - __half2float(h0));
        __half l1 = __float2half_rn(b - __half2float(h1));
        __half2 hp = __halves2half2(h0, h1);
        __half2 lp = __halves2half2(l0, l1);
        hw[p] = *reinterpret_cast<uint32_t*>(&hp);
        lw[p] = *reinterpret_cast<uint32_t*>(&lp);
    }
    const size_t oi = ((size_t)row * DINNER + j0) >> 3;
    g_yh[oi] = make_uint4(hw[0], hw[1], hw[2], hw[3]);
    g_yl[oi] = make_uint4(lw[0], lw[1], lw[2], lw[3]);
}

// ---------------- host launcher ----------------
extern "C" void kernel_launch(void* const* d_in, const int* in_sizes, int n_in,
                              void* d_out, int out_size)
{
    const float* u          = (const float*)d_in[0];
    const float* in_proj_w  = (const float*)d_in[1];
    const float* conv_w     = (const float*)d_in[2];
    const float* conv_b     = (const float*)d_in[3];
    const float* init_state = (const float*)d_in[4];
    const float* dt_bias    = (const float*)d_in[5];
    const float* A_log      = (const float*)d_in[6];
    const float* Dv         = (const float*)d_in[7];
    const float* norm_w     = (const float*)d_in[8];
    const float* out_proj_w = (const float*)d_in[9];
    float* out = (float*)d_out;

    float* zx_ptr = nullptr;
    uint4 *uhi, *ulo, *wif, *yh, *yl, *wof;
    cudaGetSymbolAddress((void**)&zx_ptr, g_zx);
    cudaGetSymbolAddress((void**)&uhi, g_uhi);
    cudaGetSymbolAddress((void**)&ulo, g_ulo);
    cudaGetSymbolAddress((void**)&wif, g_wif);
    cudaGetSymbolAddress((void**)&yh,  g_yh);
    cudaGetSymbolAddress((void**)&yl,  g_yl);
    cudaGetSymbolAddress((void**)&wof, g_wof);

    const int ssm_smem = (4 * 64 * SMP + 3 * 64) * sizeof(float);
    cudaFuncSetAttribute(ssm_chunk_kernel, cudaFuncAttributeMaxDynamicSharedMemorySize, ssm_smem);
    cudaFuncSetAttribute(gemm_mma2, cudaFuncAttributeMaxDynamicSharedMemorySize, MMA_SMEM);

    // 0. precision conversions
    {
        int n8 = BL * DMODEL / 8;                 // u -> fp16 hi/lo (exact 2-term)
        split2_fp16_kernel<<<(n8 + 255) / 256, 256>>>(u, uhi, ulo, n8, 7, BL);
        n8 = DPROJ_PAD * DMODEL / 8;              // in_proj w -> single fp16
        split1_fp16_kernel<<<(n8 + 255) / 256, 256>>>(in_proj_w, wif, n8, 7, DPROJ);
        n8 = DMODEL * DINNER / 8;                 // out_proj w -> single fp16
        split1_fp16_kernel<<<(n8 + 255) / 256, 256>>>(out_proj_w, wof, n8, 8, DMODEL);
    }
    // 1. in_proj GEMM (mma.sync fp16 x2): 16384 x 4352 x 1024
    gemm_mma2<<<dim3(DPROJ_PAD / 128, BL / 128), 256, MMA_SMEM>>>(
        uhi, ulo, wif, zx_ptr, DMODEL, DPROJ_PAD);
    // 2. conv1d + SiLU
    conv_silu_kernel<<<dim3(CONVDIM / 128, BL), 128>>>(conv_w, conv_b);
    // 3. dt softplus
    dt_kernel<<<(BL * NHEADS + 255) / 256, 256>>>(dt_bias);
    // 4. per-chunk SSM
    ssm_chunk_kernel<<<dim3(NCHUNK, NHEADS, B_SZ), 256, ssm_smem>>>(A_log);
    // 5. inter-chunk recurrence
    ssm_state_scan<<<B_SZ * NHEADS, 256>>>(init_state);
    // 6. Y_off + combine
    ssm_out_kernel<<<dim3(NCHUNK, NHEADS, B_SZ), 256>>>(Dv);
    // 7. gate + rmsnorm (+ fp16 split of y)
    gate_norm_kernel<<<BL, 256>>>(norm_w);
    // 8. out_proj GEMM: 16384 x 1024 x 2048
    gemm_mma2<<<dim3(DMODEL / 128, BL / 128), 256, MMA_SMEM>>>(
        yh, yl, wof, out, DINNER, DMODEL);
}

// round 16
// speedup vs baseline: 2.3579x; 1.0446x over previous
#include <cuda_runtime.h>
#include <cuda_fp16.h>
#include <stdint.h>
#include <cstdint>
#include <math.h>

#define B_SZ     4
#define L_SZ     4096
#define BL       (B_SZ * L_SZ)
#define DMODEL   1024
#define DINNER   2048
#define NHEADS   32
#define HDIM     64
#define DSTATE   64
#define CONVDIM  2176
#define DPROJ    4256
#define DPROJ_PAD 4352
#define NCHUNK   64
#define CHUNK_T  64
#define SMP      68

// ---------------- scratch (device globals) ----------------
__device__ float g_zx[(size_t)BL * DPROJ_PAD];
__device__ float g_xbc[(size_t)BL * CONVDIM];
__device__ float g_dt[(size_t)B_SZ * NHEADS * L_SZ];
__device__ float g_states[(size_t)B_SZ * NCHUNK * NHEADS * HDIM * DSTATE];
__device__ float g_acs[(size_t)B_SZ * NHEADS * NCHUNK * CHUNK_T];
__device__ float g_y[(size_t)BL * DINNER];

// fp16 buffers (uint4 = 8 halfs, 16B aligned)
__device__ uint4 g_uhi[(size_t)BL * DMODEL / 8];
__device__ uint4 g_ulo[(size_t)BL * DMODEL / 8];
__device__ uint4 g_wif[(size_t)DPROJ_PAD * DMODEL / 8];
__device__ uint4 g_yh [(size_t)BL * DINNER / 8];
__device__ uint4 g_yl [(size_t)BL * DINNER / 8];
__device__ uint4 g_wof[(size_t)DMODEL * DINNER / 8];

// ---------------- helpers ----------------
__device__ __forceinline__ uint32_t cvta_smem(const void* p) {
    uint32_t a;
    asm("{ .reg .u64 t; cvta.to.shared.u64 t, %1; cvt.u32.u64 %0, t; }" : "=r"(a) : "l"(p));
    return a;
}
__device__ __forceinline__ void cpasync16(uint32_t dst, const void* src) {
    asm volatile("cp.async.cg.shared.global [%0], [%1], 16;" :: "r"(dst), "l"(src));
}
__device__ __forceinline__ void cp_commit() {
    asm volatile("cp.async.commit_group;" ::: "memory");
}
template <int N> __device__ __forceinline__ void cp_wait() {
    asm volatile("cp.async.wait_group %0;" :: "n"(N) : "memory");
}
#define LDSM4(r, addr) \
    asm volatile("ldmatrix.sync.aligned.m8n8.x4.shared.b16 {%0,%1,%2,%3}, [%4];" \
        : "=r"((r)[0]), "=r"((r)[1]), "=r"((r)[2]), "=r"((r)[3]) : "r"(addr))
#define MMA16816(acc, a, b0, b1) \
    asm volatile("mma.sync.aligned.m16n8k16.row.col.f32.f16.f16.f32 " \
        "{%0,%1,%2,%3}, {%4,%5,%6,%7}, {%8,%9}, {%0,%1,%2,%3};" \
        : "+f"((acc)[0]), "+f"((acc)[1]), "+f"((acc)[2]), "+f"((acc)[3]) \
        : "r"((a)[0]), "r"((a)[1]), "r"((a)[2]), "r"((a)[3]), "r"(b0), "r"(b1))

// ---------------- fp32 -> fp16 hi/lo split (2-term, exact A) ----------------
__global__ __launch_bounds__(256) void split2_fp16_kernel(
    const float* __restrict__ src, uint4* __restrict__ hi, uint4* __restrict__ lo,
    int n8, int rowShift, int realRows)
{
    int idx = blockIdx.x * 256 + threadIdx.x;
    if (idx >= n8) return;
    int row = idx >> rowShift;
    uint4 H = make_uint4(0, 0, 0, 0), L = make_uint4(0, 0, 0, 0);
    if (row < realRows) {
        float4 a = ((const float4*)src)[2 * (size_t)idx];
        float4 b = ((const float4*)src)[2 * (size_t)idx + 1];
        float v[8] = {a.x, a.y, a.z, a.w, b.x, b.y, b.z, b.w};
        uint32_t hw[4], lw[4];
        #pragma unroll
        for (int p = 0; p < 4; p++) {
            __half h0 = __float2half_rn(v[2 * p]);
            __half h1 = __float2half_rn(v[2 * p + 1]);
            __half l0 = __float2half_rn(v[2 * p] - __half2float(h0));
            __half l1 = __float2half_rn(v[2 * p + 1] - __half2float(h1));
            __half2 hp = __halves2half2(h0, h1);
            __half2 lp = __halves2half2(l0, l1);
            hw[p] = *reinterpret_cast<uint32_t*>(&hp);
            lw[p] = *reinterpret_cast<uint32_t*>(&lp);
        }
        H = make_uint4(hw[0], hw[1], hw[2], hw[3]);
        L = make_uint4(lw[0], lw[1], lw[2], lw[3]);
    }
    hi[idx] = H;
    lo[idx] = L;
}

// ---------------- fp32 -> single fp16 (weights) ----------------
__global__ __launch_bounds__(256) void split1_fp16_kernel(
    const float* __restrict__ src, uint4* __restrict__ out,
    int n8, int rowShift, int realRows)
{
    int idx = blockIdx.x * 256 + threadIdx.x;
    if (idx >= n8) return;
    int row = idx >> rowShift;
    uint4 H = make_uint4(0, 0, 0, 0);
    if (row < realRows) {
        float4 a = ((const float4*)src)[2 * (size_t)idx];
        float4 b = ((const float4*)src)[2 * (size_t)idx + 1];
        float v[8] = {a.x, a.y, a.z, a.w, b.x, b.y, b.z, b.w};
        uint32_t hw[4];
        #pragma unroll
        for (int p = 0; p < 4; p++) {
            __half2 hp = __halves2half2(__float2half_rn(v[2 * p]), __float2half_rn(v[2 * p + 1]));
            hw[p] = *reinterpret_cast<uint32_t*>(&hp);
        }
        H = make_uint4(hw[0], hw[1], hw[2], hw[3]);
    }
    out[idx] = H;
}

// ---------------- mma.sync GEMM: C[M,N] = A[M,K] * W[N,K]^T, 2-term fp16 ----------------
// BM=128, BN=128, BK=32; 256 threads = 8 warps (4 x 2); warp tile 32x64.
// 3-stage cp.async pipeline; stage = [Ah | Al | Wf], each 128 rows x 80B.
#define ROWB      80
#define STG_MAT   (128 * ROWB)           // 10240 B
#define STG_BYTES (3 * STG_MAT)          // 30720 B
#define MMA_SMEM  (3 * STG_BYTES)        // 92160 B, 3 stages

__device__ __forceinline__ void gemm_load_stage(
    uint32_t base, const uint4* __restrict__ Ahi, const uint4* __restrict__ Alo,
    const uint4* __restrict__ Wf,
    size_t aRow0, size_t wRow0, int K8, int kt, int tid)
{
    #pragma unroll
    for (int i = 0; i < 2; i++) {
        int idx = tid + (i << 8);
        int row = idx >> 2, c = idx & 3;
        size_t gi = (aRow0 + row) * K8 + kt * 4 + c;
        uint32_t dst = base + row * ROWB + c * 16;
        cpasync16(dst,           Ahi + gi);
        cpasync16(dst + STG_MAT, Alo + gi);
    }
    #pragma unroll
    for (int i = 0; i < 2; i++) {
        int idx = tid + (i << 8);
        int row = idx >> 2, c = idx & 3;
        size_t gi = (wRow0 + row) * K8 + kt * 4 + c;
        cpasync16(base + 2 * STG_MAT + row * ROWB + c * 16, Wf + gi);
    }
}

__global__ __launch_bounds__(256, 2) void gemm_mma2(
    const uint4* __restrict__ Ahi, const uint4* __restrict__ Alo,
    const uint4* __restrict__ Wf,
    float* __restrict__ C, int K, int ldc)
{
    extern __shared__ char smch[];
    const uint32_t sb = cvta_smem(smch);
    const int tid = threadIdx.x, lane = tid & 31, wid = tid >> 5;
    const int wm = wid >> 1, wn = wid & 1;          // 4 x 2 warp grid, tile 32x64
    const int bx = blockIdx.x, by = blockIdx.y;
    const int K8 = K >> 3;
    const int NT = K >> 5;                          // BK = 32
    const size_t aRow0 = (size_t)by * 128;
    const size_t wRow0 = (size_t)bx * 128;

    float acc[2][8][4];
    #pragma unroll
    for (int mt = 0; mt < 2; mt++)
        #pragma unroll
        for (int nf = 0; nf < 8; nf++)
            #pragma unroll
            for (int e = 0; e < 4; e++) acc[mt][nf][e] = 0.f;

    gemm_load_stage(sb,             Ahi, Alo, Wf, aRow0, wRow0, K8, 0, tid);
    cp_commit();
    gemm_load_stage(sb + STG_BYTES, Ahi, Alo, Wf, aRow0, wRow0, K8, 1, tid);
    cp_commit();

    const int aLaneRow = (lane & 7) + ((lane >> 3) & 1) * 8;
    const int aLaneCol = (lane >> 4) * 16;
    const int wLaneRow = ((lane >> 4) * 8) + (lane & 7);
    const int wLaneCol = ((lane >> 3) & 1) * 16;

    int cur = 0, nxt = 2;
    for (int kt = 0; kt < NT; kt++) {
        if (kt == NT - 1) cp_wait<0>(); else cp_wait<1>();
        __syncthreads();
        const uint32_t Ab = sb + cur * STG_BYTES;
        const uint32_t Wb = Ab + 2 * STG_MAT;

        #pragma unroll
        for (int ks = 0; ks < 2; ks++) {            // two k16 steps
            uint32_t ah[2][4], al[2][4];
            #pragma unroll
            for (int mt = 0; mt < 2; mt++) {
                uint32_t addr = Ab + (wm * 32 + mt * 16 + aLaneRow) * ROWB + aLaneCol + ks * 32;
                LDSM4(ah[mt], addr);
                LDSM4(al[mt], addr + STG_MAT);
            }
            uint32_t wf[16];
            #pragma unroll
            for (int nt2 = 0; nt2 < 4; nt2++) {
                uint32_t addr = Wb + (wn * 64 + nt2 * 16 + wLaneRow) * ROWB + wLaneCol + ks * 32;
                LDSM4(wf + 4 * nt2, addr);
            }
            #pragma unroll
            for (int mt = 0; mt < 2; mt++)
                #pragma unroll
                for (int nf = 0; nf < 8; nf++) {
                    MMA16816(acc[mt][nf], ah[mt], wf[2 * nf], wf[2 * nf + 1]);
                    MMA16816(acc[mt][nf], al[mt], wf[2 * nf], wf[2 * nf + 1]);
                }
        }
        if (kt + 2 < NT) {
            gemm_load_stage(sb + nxt * STG_BYTES, Ahi, Alo, Wf, aRow0, wRow0, K8, kt + 2, tid);
            cp_commit();
        }
        cur = (cur == 2) ? 0 : cur + 1;
        nxt = (nxt == 2) ? 0 : nxt + 1;
    }

    const int rBase = by * 128 + wm * 32 + (lane >> 2);
    const int cBase = bx * 128 + wn * 64 + (lane & 3) * 2;
    #pragma unroll
    for (int mt = 0; mt < 2; mt++)
        #pragma unroll
        for (int nf = 0; nf < 8; nf++) {
            float* p0 = C + (size_t)(rBase + mt * 16)     * ldc + cBase + nf * 8;
            float* p1 = C + (size_t)(rBase + mt * 16 + 8) * ldc + cBase + nf * 8;
            p0[0] = acc[mt][nf][0]; p0[1] = acc[mt][nf][1];
            p1[0] = acc[mt][nf][2]; p1[1] = acc[mt][nf][3];
        }
}

// ---------------- conv1d(k=4) + SiLU ----------------
__global__ __launch_bounds__(128) void conv_silu_kernel(
    const float* __restrict__ cw, const float* __restrict__ cb)
{
    const int c = blockIdx.x * 128 + threadIdx.x;
    const int bl = blockIdx.y;
    if (c >= CONVDIM) return;
    const int b = bl >> 12, l = bl & 4095;
    float w0 = cw[c * 4 + 0], w1 = cw[c * 4 + 1], w2 = cw[c * 4 + 2], w3 = cw[c * 4 + 3];
    const float* base = g_zx + (size_t)(b * L_SZ) * DPROJ_PAD + 2048 + c;
    float acc = cb[c];
    if (l >= 3) acc += base[(size_t)(l - 3) * DPROJ_PAD] * w0;
    if (l >= 2) acc += base[(size_t)(l - 2) * DPROJ_PAD] * w1;
    if (l >= 1) acc += base[(size_t)(l - 1) * DPROJ_PAD] * w2;
    acc += base[(size_t)l * DPROJ_PAD] * w3;
    acc = acc / (1.f + __expf(-acc));
    g_xbc[(size_t)bl * CONVDIM + c] = acc;
}

// ---------------- dt = softplus(raw + bias), stored [b][h][l] ----------------
__global__ __launch_bounds__(256) void dt_kernel(const float* __restrict__ dt_bias)
{
    const int idx = blockIdx.x * 256 + threadIdx.x;
    if (idx >= BL * NHEADS) return;
    const int bl = idx >> 5, h = idx & 31;
    float v = g_zx[(size_t)bl * DPROJ_PAD + 4224 + h] + dt_bias[h];
    float sp = (v > 20.f) ? v : log1pf(__expf(v));
    const int b = bl >> 12, l = bl & 4095;
    g_dt[((size_t)(b * NHEADS + h) << 12) + l] = sp;
}

// ---------------- per-chunk SSM: Y_diag + chunk states ----------------
__global__ __launch_bounds__(256) void ssm_chunk_kernel(const float* __restrict__ A_log)
{
    extern __shared__ float sm[];
    float* Bt  = sm;
    float* Ct  = Bt + 64 * SMP;
    float* Xs  = Ct + 64 * SMP;
    float* Gs  = Xs + 64 * SMP;
    float* cs  = Gs + 64 * SMP;
    float* dec = cs + 64;
    float* dts = dec + 64;

    const int ch = blockIdx.x, h = blockIdx.y, b = blockIdx.z;
    const int tid = threadIdx.x;
    const int l0 = ch * CHUNK_T;

    if (tid < 64) {
        float dtv = g_dt[((size_t)(b * NHEADS + h) << 12) + l0 + tid];
        dts[tid] = dtv;
        float v = -__expf(A_log[h]) * dtv;
        #pragma unroll
        for (int o = 1; o < 32; o <<= 1) {
            float u = __shfl_up_sync(0xffffffffu, v, o);
            if ((tid & 31) >= o) v += u;
        }
        cs[tid] = v;
    }
    __syncthreads();
    if (tid >= 32 && tid < 64) cs[tid] += cs[31];
    __syncthreads();
    if (tid < 64) {
        dec[tid] = __expf(cs[63] - cs[tid]);
        g_acs[(size_t)((b * NHEADS + h) * NCHUNK + ch) * CHUNK_T + tid] = cs[tid];
    }
    for (int e = tid; e < 64 * 64; e += 256) {
        const int t = e >> 6, n = e & 63;
        const float* xb = g_xbc + (size_t)(b * L_SZ + l0 + t) * CONVDIM;
        Bt[n * SMP + t] = xb[2048 + n];
        Ct[n * SMP + t] = xb[2112 + n];
        Xs[t * SMP + n] = xb[h * HDIM + n] * dts[t];
    }
    __syncthreads();

    const int tx = tid & 15, ty = tid >> 4;
    const int i0 = ty * 4, j0 = tx * 4;

    float accG[4][4] = {};
    #pragma unroll 8
    for (int k = 0; k < 64; k++) {
        float cf[4], bf[4];
        *(float4*)cf = *(const float4*)&Ct[k * SMP + i0];
        *(float4*)bf = *(const float4*)&Bt[k * SMP + j0];
        #pragma unroll
        for (int a = 0; a < 4; a++)
            #pragma unroll
            for (int q = 0; q < 4; q++)
                accG[a][q] += cf[a] * bf[q];
    }
    #pragma unroll
    for (int a = 0; a < 4; a++) {
        const int i = i0 + a;
        float gv[4];
        #pragma unroll
        for (int q = 0; q < 4; q++) {
            const int j = j0 + q;
            gv[q] = (i >= j) ? accG[a][q] * __expf(cs[i] - cs[j]) : 0.f;
        }
        *(float4*)&Gs[i * SMP + j0] = *(float4*)gv;
    }
    __syncthreads();

    float accY[4][4] = {};
    #pragma unroll 4
    for (int k = 0; k < 64; k += 4) {
        float xv[4][4];
        #pragma unroll
        for (int kk = 0; kk < 4; kk++)
            *(float4*)xv[kk] = *(const float4*)&Xs[(k + kk) * SMP + j0];
        #pragma unroll
        for (int a = 0; a < 4; a++) {
            float gv[4];
            *(float4*)gv = *(const float4*)&Gs[(i0 + a) * SMP + k];
            #pragma unroll
            for (int kk = 0; kk < 4; kk++)
                #pragma unroll
                for (int q = 0; q < 4; q++)
                    accY[a][q] += gv[kk] * xv[kk][q];
        }
    }
    #pragma unroll
    for (int a = 0; a < 4; a++) {
        const size_t bl = (size_t)(b * L_SZ + l0 + i0 + a);
        *(float4*)&g_y[bl * DINNER + h * HDIM + j0] = *(float4*)accY[a];
    }

    float accS[4][4] = {};
    #pragma unroll 8
    for (int t = 0; t < 64; t++) {
        const float d = dec[t];
        float xv[4];
        *(float4*)xv = *(const float4*)&Xs[t * SMP + j0];
        float bd[4];
        #pragma unroll
        for (int a = 0; a < 4; a++) bd[a] = Bt[(i0 + a) * SMP + t] * d;
        #pragma unroll
        for (int a = 0; a < 4; a++)
            #pragma unroll
            for (int q = 0; q < 4; q++)
                accS[a][q] += bd[a] * xv[q];
    }
    const size_t sbase = ((size_t)(b * NCHUNK + ch) * NHEADS + h) * (HDIM * DSTATE);
    #pragma unroll
    for (int a = 0; a < 4; a++)
        *(float4*)&g_states[sbase + (size_t)(i0 + a) * HDIM + j0] = *(float4*)accS[a];
}

// ---------------- inter-chunk state recurrence ----------------
__global__ __launch_bounds__(256) void ssm_state_scan(const float* __restrict__ init_states)
{
    const int bh = blockIdx.x;
    const int b = bh >> 5, h = bh & 31;
    const int tid = threadIdx.x;
    float S[16];
    #pragma unroll
    for (int r = 0; r < 16; r++) {
        const int e = tid + (r << 8);
        const int n = e >> 6, p = e & 63;
        S[r] = init_states[h * (HDIM * DSTATE) + p * DSTATE + n];
    }
    const float* acs = g_acs + (size_t)(b * NHEADS + h) * NCHUNK * CHUNK_T;
    for (int ch = 0; ch < NCHUNK; ch++) {
        const float aexp = __expf(acs[ch * CHUNK_T + 63]);
        float* st = g_states + ((size_t)(b * NCHUNK + ch) * NHEADS + h) * (HDIM * DSTATE);
        #pragma unroll
        for (int r = 0; r < 16; r++) {
            const int e = tid + (r << 8);
            const float tmp = st[e];
            st[e] = S[r];
            S[r] = aexp * S[r] + tmp;
        }
    }
}

// ---------------- Y_off = C @ S_in * exp(cs) ; final Y ----------------
__global__ __launch_bounds__(256) void ssm_out_kernel(const float* __restrict__ Dvec)
{
    __shared__ float Ct[64 * SMP];
    __shared__ float Ss[64 * SMP];
    __shared__ float scs[64];
    const int ch = blockIdx.x, h = blockIdx.y, b = blockIdx.z;
    const int tid = threadIdx.x;
    const int l0 = ch * CHUNK_T;
    const size_t sbase = ((size_t)(b * NCHUNK + ch) * NHEADS + h) * (HDIM * DSTATE);

    if (tid < 64)
        scs[tid] = __expf(g_acs[(size_t)((b * NHEADS + h) * NCHUNK + ch) * CHUNK_T + tid]);
    for (int e = tid; e < 64 * 64; e += 256) {
        const int t = e >> 6, n = e & 63;
        Ct[n * SMP + t] = g_xbc[(size_t)(b * L_SZ + l0 + t) * CONVDIM + 2112 + n];
        Ss[t * SMP + n] = g_states[sbase + e];
    }
    __syncthreads();

    const int tx = tid & 15, ty = tid >> 4;
    const int i0 = ty * 4, j0 = tx * 4;
    float acc[4][4] = {};
    #pragma unroll 8
    for (int k = 0; k < 64; k++) {
        float cf[4], sv[4];
        *(float4*)cf = *(const float4*)&Ct[k * SMP + i0];
        *(float4*)sv = *(const float4*)&Ss[k * SMP + j0];
        #pragma unroll
        for (int a = 0; a < 4; a++)
            #pragma unroll
            for (int q = 0; q < 4; q++)
                acc[a][q] += cf[a] * sv[q];
    }
    const float Dh = Dvec[h];
    #pragma unroll
    for (int a = 0; a < 4; a++) {
        const int t = i0 + a;
        const size_t bl = (size_t)(b * L_SZ + l0 + t);
        const float sc = scs[t];
        float yv[4], xv[4];
        *(float4*)yv = *(const float4*)&g_y[bl * DINNER + h * HDIM + j0];
        *(float4*)xv = *(const float4*)&g_xbc[bl * CONVDIM + h * HDIM + j0];
        #pragma unroll
        for (int q = 0; q < 4; q++)
            yv[q] = yv[q] + acc[a][q] * sc + xv[q] * Dh;
        *(float4*)&g_y[bl * DINNER + h * HDIM + j0] = *(float4*)yv;
    }
}

// ---------------- gated SiLU + RMSNorm, output split to fp16 hi/lo ----------------
__global__ __launch_bounds__(256) void gate_norm_kernel(const float* __restrict__ norm_w)
{
    __shared__ float rsh[9];
    const int row = blockIdx.x, tid = threadIdx.x;
    const float* zr = g_zx + (size_t)row * DPROJ_PAD;
    const float* yr = g_y + (size_t)row * DINNER;
    const int j0 = tid * 8;

    float4 z0 = *(const float4*)(zr + j0), z1 = *(const float4*)(zr + j0 + 4);
    float4 y0 = *(const float4*)(yr + j0), y1 = *(const float4*)(yr + j0 + 4);
    float zz[8] = {z0.x, z0.y, z0.z, z0.w, z1.x, z1.y, z1.z, z1.w};
    float yy[8] = {y0.x, y0.y, y0.z, y0.w, y1.x, y1.y, y1.z, y1.w};
    float v[8];
    float local = 0.f;
    #pragma unroll
    for (int j = 0; j < 8; j++) {
        const float s = zz[j] / (1.f + __expf(-zz[j]));
        v[j] = yy[j] * s;
        local += v[j] * v[j];
    }
    #pragma unroll
    for (int o = 16; o > 0; o >>= 1) local += __shfl_down_sync(0xffffffffu, local, o);
    if ((tid & 31) == 0) rsh[tid >> 5] = local;
    __syncthreads();
    if (tid == 0) {
        float s = 0.f;
        for (int w = 0; w < 8; w++) s += rsh[w];
        rsh[8] = rsqrtf(s / (float)DINNER + 1e-5f);
    }
    __syncthreads();
    const float scale = rsh[8];

    float4 w0 = *(const float4*)(norm_w + j0), w1 = *(const float4*)(norm_w + j0 + 4);
    float ww[8] = {w0.x, w0.y, w0.z, w0.w, w1.x, w1.y, w1.z, w1.w};
    uint32_t hw[4], lw[4];
    #pragma unroll
    for (int p = 0; p < 4; p++) {
        float a = v[2 * p] * scale * ww[2 * p];
        float b = v[2 * p + 1] * scale * ww[2 * p + 1];
        __half h0 = __float2half_rn(a);
        __half h1 = __float2half_rn(b);
        __half l0 = __float2half_rn(a - __half2float(h0));
        __half l1 = __float2half_rn(b - __half2float(h1));
        __half2 hp = __halves2half2(h0, h1);
        __half2 lp = __halves2half2(l0, l1);
        hw[p] = *reinterpret_cast<uint32_t*>(&hp);
        lw[p] = *reinterpret_cast<uint32_t*>(&lp);
    }
    const size_t oi = ((size_t)row * DINNER + j0) >> 3;
    g_yh[oi] = make_uint4(hw[0], hw[1], hw[2], hw[3]);
    g_yl[oi] = make_uint4(lw[0], lw[1], lw[2], lw[3]);
}

// ---------------- host launcher ----------------
extern "C" void kernel_launch(void* const* d_in, const int* in_sizes, int n_in,
                              void* d_out, int out_size)
{
    const float* u          = (const float*)d_in[0];
    const float* in_proj_w  = (const float*)d_in[1];
    const float* conv_w     = (const float*)d_in[2];
    const float* conv_b     = (const float*)d_in[3];
    const float* init_state = (const float*)d_in[4];
    const float* dt_bias    = (const float*)d_in[5];
    const float* A_log      = (const float*)d_in[6];
    const float* Dv         = (const float*)d_in[7];
    const float* norm_w     = (const float*)d_in[8];
    const float* out_proj_w = (const float*)d_in[9];
    float* out = (float*)d_out;

    float* zx_ptr = nullptr;
    uint4 *uhi, *ulo, *wif, *yh, *yl, *wof;
    cudaGetSymbolAddress((void**)&zx_ptr, g_zx);
    cudaGetSymbolAddress((void**)&uhi, g_uhi);
    cudaGetSymbolAddress((void**)&ulo, g_ulo);
    cudaGetSymbolAddress((void**)&wif, g_wif);
    cudaGetSymbolAddress((void**)&yh,  g_yh);
    cudaGetSymbolAddress((void**)&yl,  g_yl);
    cudaGetSymbolAddress((void**)&wof, g_wof);

    const int ssm_smem = (4 * 64 * SMP + 3 * 64) * sizeof(float);
    cudaFuncSetAttribute(ssm_chunk_kernel, cudaFuncAttributeMaxDynamicSharedMemorySize, ssm_smem);
    cudaFuncSetAttribute(gemm_mma2, cudaFuncAttributeMaxDynamicSharedMemorySize, MMA_SMEM);

    // 0. precision conversions
    {
        int n8 = BL * DMODEL / 8;                 // u -> fp16 hi/lo (exact 2-term)
        split2_fp16_kernel<<<(n8 + 255) / 256, 256>>>(u, uhi, ulo, n8, 7, BL);
        n8 = DPROJ_PAD * DMODEL / 8;              // in_proj w -> single fp16
        split1_fp16_kernel<<<(n8 + 255) / 256, 256>>>(in_proj_w, wif, n8, 7, DPROJ);
        n8 = DMODEL * DINNER / 8;                 // out_proj w -> single fp16
        split1_fp16_kernel<<<(n8 + 255) / 256, 256>>>(out_proj_w, wof, n8, 8, DMODEL);
    }
    // 1. in_proj GEMM (mma.sync fp16 x2): 16384 x 4352 x 1024
    gemm_mma2<<<dim3(DPROJ_PAD / 128, BL / 128), 256, MMA_SMEM>>>(
        uhi, ulo, wif, zx_ptr, DMODEL, DPROJ_PAD);
    // 2. conv1d + SiLU
    conv_silu_kernel<<<dim3(CONVDIM / 128, BL), 128>>>(conv_w, conv_b);
    // 3. dt softplus
    dt_kernel<<<(BL * NHEADS + 255) / 256, 256>>>(dt_bias);
    // 4. per-chunk SSM
    ssm_chunk_kernel<<<dim3(NCHUNK, NHEADS, B_SZ), 256, ssm_smem>>>(A_log);
    // 5. inter-chunk recurrence
    ssm_state_scan<<<B_SZ * NHEADS, 256>>>(init_state);
    // 6. Y_off + combine
    ssm_out_kernel<<<dim3(NCHUNK, NHEADS, B_SZ), 256>>>(Dv);
    // 7. gate + rmsnorm (+ fp16 split of y)
    gate_norm_kernel<<<BL, 256>>>(norm_w);
    // 8. out_proj GEMM: 16384 x 1024 x 2048
    gemm_mma2<<<dim3(DMODEL / 128, BL / 128), 256, MMA_SMEM>>>(
        yh, yl, wof, out, DINNER, DMODEL);
}

// round 17
// speedup vs baseline: 2.7909x; 1.1836x over previous
#include <cuda_runtime.h>
#include <cuda_fp16.h>
#include <stdint.h>
#include <cstdint>
#include <math.h>

#define B_SZ     4
#define L_SZ     4096
#define BL       (B_SZ * L_SZ)
#define DMODEL   1024
#define DINNER   2048
#define NHEADS   32
#define HDIM     64
#define DSTATE   64
#define CONVDIM  2176
#define DPROJ    4256
#define DPROJ_PAD 4352
#define NCHUNK   64
#define CHUNK_T  64
#define SMP      68

// ---------------- scratch (device globals) ----------------
__device__ float g_zx[(size_t)BL * DPROJ_PAD];
__device__ float g_xbc[(size_t)BL * CONVDIM];
__device__ float g_dt[(size_t)B_SZ * NHEADS * L_SZ];
__device__ float g_states[(size_t)B_SZ * NCHUNK * NHEADS * HDIM * DSTATE];
__device__ float g_acs[(size_t)B_SZ * NHEADS * NCHUNK * CHUNK_T];
__device__ float g_y[(size_t)BL * DINNER];

// fp16 buffers (uint4 = 8 halfs, 16B aligned)
__device__ uint4 g_uf [(size_t)BL * DMODEL / 8];
__device__ uint4 g_wif[(size_t)DPROJ_PAD * DMODEL / 8];
__device__ uint4 g_yf [(size_t)BL * DINNER / 8];
__device__ uint4 g_wof[(size_t)DMODEL * DINNER / 8];

// ---------------- helpers ----------------
__device__ __forceinline__ uint32_t cvta_smem(const void* p) {
    uint32_t a;
    asm("{ .reg .u64 t; cvta.to.shared.u64 t, %1; cvt.u32.u64 %0, t; }" : "=r"(a) : "l"(p));
    return a;
}
__device__ __forceinline__ void cpasync16(uint32_t dst, const void* src) {
    asm volatile("cp.async.cg.shared.global [%0], [%1], 16;" :: "r"(dst), "l"(src));
}
__device__ __forceinline__ void cp_commit() {
    asm volatile("cp.async.commit_group;" ::: "memory");
}
template <int N> __device__ __forceinline__ void cp_wait() {
    asm volatile("cp.async.wait_group %0;" :: "n"(N) : "memory");
}
#define LDSM4(r, addr) \
    asm volatile("ldmatrix.sync.aligned.m8n8.x4.shared.b16 {%0,%1,%2,%3}, [%4];" \
        : "=r"((r)[0]), "=r"((r)[1]), "=r"((r)[2]), "=r"((r)[3]) : "r"(addr))
#define MMA16816(acc, a, b0, b1) \
    asm volatile("mma.sync.aligned.m16n8k16.row.col.f32.f16.f16.f32 " \
        "{%0,%1,%2,%3}, {%4,%5,%6,%7}, {%8,%9}, {%0,%1,%2,%3};" \
        : "+f"((acc)[0]), "+f"((acc)[1]), "+f"((acc)[2]), "+f"((acc)[3]) \
        : "r"((a)[0]), "r"((a)[1]), "r"((a)[2]), "r"((a)[3]), "r"(b0), "r"(b1))

// ---------------- fp32 -> single fp16 ----------------
__global__ __launch_bounds__(256) void split1_fp16_kernel(
    const float* __restrict__ src, uint4* __restrict__ out,
    int n8, int rowShift, int realRows)
{
    int idx = blockIdx.x * 256 + threadIdx.x;
    if (idx >= n8) return;
    int row = idx >> rowShift;
    uint4 H = make_uint4(0, 0, 0, 0);
    if (row < realRows) {
        float4 a = ((const float4*)src)[2 * (size_t)idx];
        float4 b = ((const float4*)src)[2 * (size_t)idx + 1];
        float v[8] = {a.x, a.y, a.z, a.w, b.x, b.y, b.z, b.w};
        uint32_t hw[4];
        #pragma unroll
        for (int p = 0; p < 4; p++) {
            __half2 hp = __halves2half2(__float2half_rn(v[2 * p]), __float2half_rn(v[2 * p + 1]));
            hw[p] = *reinterpret_cast<uint32_t*>(&hp);
        }
        H = make_uint4(hw[0], hw[1], hw[2], hw[3]);
    }
    out[idx] = H;
}

// ---------------- mma.sync GEMM: C[M,N] = A[M,K] * W[N,K]^T, single fp16 ----------------
// BM=128, BN=128, BK=32; 256 threads = 8 warps (4 x 2); warp tile 32x64.
// 3-stage cp.async pipeline; stage = [Af | Wf], each 128 rows x 80B.
#define ROWB      80
#define STG_MAT   (128 * ROWB)           // 10240 B
#define STG_BYTES (2 * STG_MAT)          // 20480 B
#define MMA_SMEM  (3 * STG_BYTES)        // 61440 B, 3 stages

__device__ __forceinline__ void gemm_load_stage(
    uint32_t base, const uint4* __restrict__ Af, const uint4* __restrict__ Wf,
    size_t aRow0, size_t wRow0, int K8, int kt, int tid)
{
    #pragma unroll
    for (int i = 0; i < 2; i++) {
        int idx = tid + (i << 8);
        int row = idx >> 2, c = idx & 3;
        size_t gi = (aRow0 + row) * K8 + kt * 4 + c;
        cpasync16(base + row * ROWB + c * 16, Af + gi);
    }
    #pragma unroll
    for (int i = 0; i < 2; i++) {
        int idx = tid + (i << 8);
        int row = idx >> 2, c = idx & 3;
        size_t gi = (wRow0 + row) * K8 + kt * 4 + c;
        cpasync16(base + STG_MAT + row * ROWB + c * 16, Wf + gi);
    }
}

__global__ __launch_bounds__(256, 2) void gemm_mma1(
    const uint4* __restrict__ Af, const uint4* __restrict__ Wf,
    float* __restrict__ C, int K, int ldc)
{
    extern __shared__ char smch[];
    const uint32_t sb = cvta_smem(smch);
    const int tid = threadIdx.x, lane = tid & 31, wid = tid >> 5;
    const int wm = wid >> 1, wn = wid & 1;          // 4 x 2 warp grid, tile 32x64
    const int bx = blockIdx.x, by = blockIdx.y;
    const int K8 = K >> 3;
    const int NT = K >> 5;                          // BK = 32
    const size_t aRow0 = (size_t)by * 128;
    const size_t wRow0 = (size_t)bx * 128;

    float acc[2][8][4];
    #pragma unroll
    for (int mt = 0; mt < 2; mt++)
        #pragma unroll
        for (int nf = 0; nf < 8; nf++)
            #pragma unroll
            for (int e = 0; e < 4; e++) acc[mt][nf][e] = 0.f;

    gemm_load_stage(sb,             Af, Wf, aRow0, wRow0, K8, 0, tid);
    cp_commit();
    gemm_load_stage(sb + STG_BYTES, Af, Wf, aRow0, wRow0, K8, 1, tid);
    cp_commit();

    const int aLaneRow = (lane & 7) + ((lane >> 3) & 1) * 8;
    const int aLaneCol = (lane >> 4) * 16;
    const int wLaneRow = ((lane >> 4) * 8) + (lane & 7);
    const int wLaneCol = ((lane >> 3) & 1) * 16;

    int cur = 0, nxt = 2;
    for (int kt = 0; kt < NT; kt++) {
        if (kt == NT - 1) cp_wait<0>(); else cp_wait<1>();
        __syncthreads();
        const uint32_t Ab = sb + cur * STG_BYTES;
        const uint32_t Wb = Ab + STG_MAT;

        #pragma unroll
        for (int ks = 0; ks < 2; ks++) {            // two k16 steps
            uint32_t ah[2][4];
            #pragma unroll
            for (int mt = 0; mt < 2; mt++) {
                uint32_t addr = Ab + (wm * 32 + mt * 16 + aLaneRow) * ROWB + aLaneCol + ks * 32;
                LDSM4(ah[mt], addr);
            }
            uint32_t wf[16];
            #pragma unroll
            for (int nt2 = 0; nt2 < 4; nt2++) {
                uint32_t addr = Wb + (wn * 64 + nt2 * 16 + wLaneRow) * ROWB + wLaneCol + ks * 32;
                LDSM4(wf + 4 * nt2, addr);
            }
            #pragma unroll
            for (int mt = 0; mt < 2; mt++)
                #pragma unroll
                for (int nf = 0; nf < 8; nf++)
                    MMA16816(acc[mt][nf], ah[mt], wf[2 * nf], wf[2 * nf + 1]);
        }
        if (kt + 2 < NT) {
            gemm_load_stage(sb + nxt * STG_BYTES, Af, Wf, aRow0, wRow0, K8, kt + 2, tid);
            cp_commit();
        }
        cur = (cur == 2) ? 0 : cur + 1;
        nxt = (nxt == 2) ? 0 : nxt + 1;
    }

    const int rBase = by * 128 + wm * 32 + (lane >> 2);
    const int cBase = bx * 128 + wn * 64 + (lane & 3) * 2;
    #pragma unroll
    for (int mt = 0; mt < 2; mt++)
        #pragma unroll
        for (int nf = 0; nf < 8; nf++) {
            float* p0 = C + (size_t)(rBase + mt * 16)     * ldc + cBase + nf * 8;
            float* p1 = C + (size_t)(rBase + mt * 16 + 8) * ldc + cBase + nf * 8;
            p0[0] = acc[mt][nf][0]; p0[1] = acc[mt][nf][1];
            p1[0] = acc[mt][nf][2]; p1[1] = acc[mt][nf][3];
        }
}

// ---------------- conv1d(k=4) + SiLU ----------------
__global__ __launch_bounds__(128) void conv_silu_kernel(
    const float* __restrict__ cw, const float* __restrict__ cb)
{
    const int c = blockIdx.x * 128 + threadIdx.x;
    const int bl = blockIdx.y;
    if (c >= CONVDIM) return;
    const int b = bl >> 12, l = bl & 4095;
    float w0 = cw[c * 4 + 0], w1 = cw[c * 4 + 1], w2 = cw[c * 4 + 2], w3 = cw[c * 4 + 3];
    const float* base = g_zx + (size_t)(b * L_SZ) * DPROJ_PAD + 2048 + c;
    float acc = cb[c];
    if (l >= 3) acc += base[(size_t)(l - 3) * DPROJ_PAD] * w0;
    if (l >= 2) acc += base[(size_t)(l - 2) * DPROJ_PAD] * w1;
    if (l >= 1) acc += base[(size_t)(l - 1) * DPROJ_PAD] * w2;
    acc += base[(size_t)l * DPROJ_PAD] * w3;
    acc = acc / (1.f + __expf(-acc));
    g_xbc[(size_t)bl * CONVDIM + c] = acc;
}

// ---------------- dt = softplus(raw + bias), stored [b][h][l] ----------------
__global__ __launch_bounds__(256) void dt_kernel(const float* __restrict__ dt_bias)
{
    const int idx = blockIdx.x * 256 + threadIdx.x;
    if (idx >= BL * NHEADS) return;
    const int bl = idx >> 5, h = idx & 31;
    float v = g_zx[(size_t)bl * DPROJ_PAD + 4224 + h] + dt_bias[h];
    float sp = (v > 20.f) ? v : log1pf(__expf(v));
    const int b = bl >> 12, l = bl & 4095;
    g_dt[((size_t)(b * NHEADS + h) << 12) + l] = sp;
}

// ---------------- per-chunk SSM: Y_diag + chunk states ----------------
__global__ __launch_bounds__(256) void ssm_chunk_kernel(const float* __restrict__ A_log)
{
    extern __shared__ float sm[];
    float* Bt  = sm;
    float* Ct  = Bt + 64 * SMP;
    float* Xs  = Ct + 64 * SMP;
    float* Gs  = Xs + 64 * SMP;
    float* cs  = Gs + 64 * SMP;
    float* dec = cs + 64;
    float* dts = dec + 64;

    const int ch = blockIdx.x, h = blockIdx.y, b = blockIdx.z;
    const int tid = threadIdx.x;
    const int l0 = ch * CHUNK_T;

    if (tid < 64) {
        float dtv = g_dt[((size_t)(b * NHEADS + h) << 12) + l0 + tid];
        dts[tid] = dtv;
        float v = -__expf(A_log[h]) * dtv;
        #pragma unroll
        for (int o = 1; o < 32; o <<= 1) {
            float u = __shfl_up_sync(0xffffffffu, v, o);
            if ((tid & 31) >= o) v += u;
        }
        cs[tid] = v;
    }
    __syncthreads();
    if (tid >= 32 && tid < 64) cs[tid] += cs[31];
    __syncthreads();
    if (tid < 64) {
        dec[tid] = __expf(cs[63] - cs[tid]);
        g_acs[(size_t)((b * NHEADS + h) * NCHUNK + ch) * CHUNK_T + tid] = cs[tid];
    }
    for (int e = tid; e < 64 * 64; e += 256) {
        const int t = e >> 6, n = e & 63;
        const float* xb = g_xbc + (size_t)(b * L_SZ + l0 + t) * CONVDIM;
        Bt[n * SMP + t] = xb[2048 + n];
        Ct[n * SMP + t] = xb[2112 + n];
        Xs[t * SMP + n] = xb[h * HDIM + n] * dts[t];
    }
    __syncthreads();

    const int tx = tid & 15, ty = tid >> 4;
    const int i0 = ty * 4, j0 = tx * 4;

    float accG[4][4] = {};
    #pragma unroll 8
    for (int k = 0; k < 64; k++) {
        float cf[4], bf[4];
        *(float4*)cf = *(const float4*)&Ct[k * SMP + i0];
        *(float4*)bf = *(const float4*)&Bt[k * SMP + j0];
        #pragma unroll
        for (int a = 0; a < 4; a++)
            #pragma unroll
            for (int q = 0; q < 4; q++)
                accG[a][q] += cf[a] * bf[q];
    }
    #pragma unroll
    for (int a = 0; a < 4; a++) {
        const int i = i0 + a;
        float gv[4];
        #pragma unroll
        for (int q = 0; q < 4; q++) {
            const int j = j0 + q;
            gv[q] = (i >= j) ? accG[a][q] * __expf(cs[i] - cs[j]) : 0.f;
        }
        *(float4*)&Gs[i * SMP + j0] = *(float4*)gv;
    }
    __syncthreads();

    float accY[4][4] = {};
    #pragma unroll 4
    for (int k = 0; k < 64; k += 4) {
        float xv[4][4];
        #pragma unroll
        for (int kk = 0; kk < 4; kk++)
            *(float4*)xv[kk] = *(const float4*)&Xs[(k + kk) * SMP + j0];
        #pragma unroll
        for (int a = 0; a < 4; a++) {
            float gv[4];
            *(float4*)gv = *(const float4*)&Gs[(i0 + a) * SMP + k];
            #pragma unroll
            for (int kk = 0; kk < 4; kk++)
                #pragma unroll
                for (int q = 0; q < 4; q++)
                    accY[a][q] += gv[kk] * xv[kk][q];
        }
    }
    #pragma unroll
    for (int a = 0; a < 4; a++) {
        const size_t bl = (size_t)(b * L_SZ + l0 + i0 + a);
        *(float4*)&g_y[bl * DINNER + h * HDIM + j0] = *(float4*)accY[a];
    }

    float accS[4][4] = {};
    #pragma unroll 8
    for (int t = 0; t < 64; t++) {
        const float d = dec[t];
        float xv[4];
        *(float4*)xv = *(const float4*)&Xs[t * SMP + j0];
        float bd[4];
        #pragma unroll
        for (int a = 0; a < 4; a++) bd[a] = Bt[(i0 + a) * SMP + t] * d;
        #pragma unroll
        for (int a = 0; a < 4; a++)
            #pragma unroll
            for (int q = 0; q < 4; q++)
                accS[a][q] += bd[a] * xv[q];
    }
    const size_t sbase = ((size_t)(b * NCHUNK + ch) * NHEADS + h) * (HDIM * DSTATE);
    #pragma unroll
    for (int a = 0; a < 4; a++)
        *(float4*)&g_states[sbase + (size_t)(i0 + a) * HDIM + j0] = *(float4*)accS[a];
}

// ---------------- inter-chunk state recurrence ----------------
__global__ __launch_bounds__(256) void ssm_state_scan(const float* __restrict__ init_states)
{
    const int bh = blockIdx.x;
    const int b = bh >> 5, h = bh & 31;
    const int tid = threadIdx.x;
    float S[16];
    #pragma unroll
    for (int r = 0; r < 16; r++) {
        const int e = tid + (r << 8);
        const int n = e >> 6, p = e & 63;
        S[r] = init_states[h * (HDIM * DSTATE) + p * DSTATE + n];
    }
    const float* acs = g_acs + (size_t)(b * NHEADS + h) * NCHUNK * CHUNK_T;
    for (int ch = 0; ch < NCHUNK; ch++) {
        const float aexp = __expf(acs[ch * CHUNK_T + 63]);
        float* st = g_states + ((size_t)(b * NCHUNK + ch) * NHEADS + h) * (HDIM * DSTATE);
        #pragma unroll
        for (int r = 0; r < 16; r++) {
            const int e = tid + (r << 8);
            const float tmp = st[e];
            st[e] = S[r];
            S[r] = aexp * S[r] + tmp;
        }
    }
}

// ---------------- Y_off = C @ S_in * exp(cs) ; final Y ----------------
__global__ __launch_bounds__(256) void ssm_out_kernel(const float* __restrict__ Dvec)
{
    __shared__ float Ct[64 * SMP];
    __shared__ float Ss[64 * SMP];
    __shared__ float scs[64];
    const int ch = blockIdx.x, h = blockIdx.y, b = blockIdx.z;
    const int tid = threadIdx.x;
    const int l0 = ch * CHUNK_T;
    const size_t sbase = ((size_t)(b * NCHUNK + ch) * NHEADS + h) * (HDIM * DSTATE);

    if (tid < 64)
        scs[tid] = __expf(g_acs[(size_t)((b * NHEADS + h) * NCHUNK + ch) * CHUNK_T + tid]);
    for (int e = tid; e < 64 * 64; e += 256) {
        const int t = e >> 6, n = e & 63;
        Ct[n * SMP + t] = g_xbc[(size_t)(b * L_SZ + l0 + t) * CONVDIM + 2112 + n];
        Ss[t * SMP + n] = g_states[sbase + e];
    }
    __syncthreads();

    const int tx = tid & 15, ty = tid >> 4;
    const int i0 = ty * 4, j0 = tx * 4;
    float acc[4][4] = {};
    #pragma unroll 8
    for (int k = 0; k < 64; k++) {
        float cf[4], sv[4];
        *(float4*)cf = *(const float4*)&Ct[k * SMP + i0];
        *(float4*)sv = *(const float4*)&Ss[k * SMP + j0];
        #pragma unroll
        for (int a = 0; a < 4; a++)
            #pragma unroll
            for (int q = 0; q < 4; q++)
                acc[a][q] += cf[a] * sv[q];
    }
    const float Dh = Dvec[h];
    #pragma unroll
    for (int a = 0; a < 4; a++) {
        const int t = i0 + a;
        const size_t bl = (size_t)(b * L_SZ + l0 + t);
        const float sc = scs[t];
        float yv[4], xv[4];
        *(float4*)yv = *(const float4*)&g_y[bl * DINNER + h * HDIM + j0];
        *(float4*)xv = *(const float4*)&g_xbc[bl * CONVDIM + h * HDIM + j0];
        #pragma unroll
        for (int q = 0; q < 4; q++)
            yv[q] = yv[q] + acc[a][q] * sc + xv[q] * Dh;
        *(float4*)&g_y[bl * DINNER + h * HDIM + j0] = *(float4*)yv;
    }
}

// ---------------- gated SiLU + RMSNorm, output to single fp16 ----------------
__global__ __launch_bounds__(256) void gate_norm_kernel(const float* __restrict__ norm_w)
{
    __shared__ float rsh[9];
    const int row = blockIdx.x, tid = threadIdx.x;
    const float* zr = g_zx + (size_t)row * DPROJ_PAD;
    const float* yr = g_y + (size_t)row * DINNER;
    const int j0 = tid * 8;

    float4 z0 = *(const float4*)(zr + j0), z1 = *(const float4*)(zr + j0 + 4);
    float4 y0 = *(const float4*)(yr + j0), y1 = *(const float4*)(yr + j0 + 4);
    float zz[8] = {z0.x, z0.y, z0.z, z0.w, z1.x, z1.y, z1.z, z1.w};
    float yy[8] = {y0.x, y0.y, y0.z, y0.w, y1.x, y1.y, y1.z, y1.w};
    float v[8];
    float local = 0.f;
    #pragma unroll
    for (int j = 0; j < 8; j++) {
        const float s = zz[j] / (1.f + __expf(-zz[j]));
        v[j] = yy[j] * s;
        local += v[j] * v[j];
    }
    #pragma unroll
    for (int o = 16; o > 0; o >>= 1) local += __shfl_down_sync(0xffffffffu, local, o);
    if ((tid & 31) == 0) rsh[tid >> 5] = local;
    __syncthreads();
    if (tid == 0) {
        float s = 0.f;
        for (int w = 0; w < 8; w++) s += rsh[w];
        rsh[8] = rsqrtf(s / (float)DINNER + 1e-5f);
    }
    __syncthreads();
    const float scale = rsh[8];

    float4 w0 = *(const float4*)(norm_w + j0), w1 = *(const float4*)(norm_w + j0 + 4);
    float ww[8] = {w0.x, w0.y, w0.z, w0.w, w1.x, w1.y, w1.z, w1.w};
    uint32_t hw[4];
    #pragma unroll
    for (int p = 0; p < 4; p++) {
        float a = v[2 * p] * scale * ww[2 * p];
        float b = v[2 * p + 1] * scale * ww[2 * p + 1];
        __half2 hp = __halves2half2(__float2half_rn(a), __float2half_rn(b));
        hw[p] = *reinterpret_cast<uint32_t*>(&hp);
    }
    g_yf[((size_t)row * DINNER + j0) >> 3] = make_uint4(hw[0], hw[1], hw[2], hw[3]);
}

// ---------------- host launcher ----------------
extern "C" void kernel_launch(void* const* d_in, const int* in_sizes, int n_in,
                              void* d_out, int out_size)
{
    const float* u          = (const float*)d_in[0];
    const float* in_proj_w  = (const float*)d_in[1];
    const float* conv_w     = (const float*)d_in[2];
    const float* conv_b     = (const float*)d_in[3];
    const float* init_state = (const float*)d_in[4];
    const float* dt_bias    = (const float*)d_in[5];
    const float* A_log      = (const float*)d_in[6];
    const float* Dv         = (const float*)d_in[7];
    const float* norm_w     = (const float*)d_in[8];
    const float* out_proj_w = (const float*)d_in[9];
    float* out = (float*)d_out;

    float* zx_ptr = nullptr;
    uint4 *uf, *wif, *yf, *wof;
    cudaGetSymbolAddress((void**)&zx_ptr, g_zx);
    cudaGetSymbolAddress((void**)&uf,  g_uf);
    cudaGetSymbolAddress((void**)&wif, g_wif);
    cudaGetSymbolAddress((void**)&yf,  g_yf);
    cudaGetSymbolAddress((void**)&wof, g_wof);

    const int ssm_smem = (4 * 64 * SMP + 3 * 64) * sizeof(float);
    cudaFuncSetAttribute(ssm_chunk_kernel, cudaFuncAttributeMaxDynamicSharedMemorySize, ssm_smem);
    cudaFuncSetAttribute(gemm_mma1, cudaFuncAttributeMaxDynamicSharedMemorySize, MMA_SMEM);

    // 0. precision conversions (all single fp16)
    {
        int n8 = BL * DMODEL / 8;                 // u
        split1_fp16_kernel<<<(n8 + 255) / 256, 256>>>(u, uf, n8, 7, BL);
        n8 = DPROJ_PAD * DMODEL / 8;              // in_proj w (padded rows zeroed)
        split1_fp16_kernel<<<(n8 + 255) / 256, 256>>>(in_proj_w, wif, n8, 7, DPROJ);
        n8 = DMODEL * DINNER / 8;                 // out_proj w
        split1_fp16_kernel<<<(n8 + 255) / 256, 256>>>(out_proj_w, wof, n8, 8, DMODEL);
    }
    // 1. in_proj GEMM (mma.sync fp16): 16384 x 4352 x 1024
    gemm_mma1<<<dim3(DPROJ_PAD / 128, BL / 128), 256, MMA_SMEM>>>(
        uf, wif, zx_ptr, DMODEL, DPROJ_PAD);
    // 2. conv1d + SiLU
    conv_silu_kernel<<<dim3(CONVDIM / 128, BL), 128>>>(conv_w, conv_b);
    // 3. dt softplus
    dt_kernel<<<(BL * NHEADS + 255) / 256, 256>>>(dt_bias);
    // 4. per-chunk SSM
    ssm_chunk_kernel<<<dim3(NCHUNK, NHEADS, B_SZ), 256, ssm_smem>>>(A_log);
    // 5. inter-chunk recurrence
    ssm_state_scan<<<B_SZ * NHEADS, 256>>>(init_state);
    // 6. Y_off + combine
    ssm_out_kernel<<<dim3(NCHUNK, NHEADS, B_SZ), 256>>>(Dv);
    // 7. gate + rmsnorm (+ fp16 convert of y)
    gate_norm_kernel<<<BL, 256>>>(norm_w);
    // 8. out_proj GEMM: 16384 x 1024 x 2048
    gemm_mma1<<<dim3(DMODEL / 128, BL / 128), 256, MMA_SMEM>>>(
        yf, wof, out, DINNER, DMODEL);
}